// round 12
// baseline (speedup 1.0000x reference)
#include <cuda_runtime.h>

#define BSZ   4
#define TGT   512
#define KVLEN 4096
#define KVOLD (KVLEN - TGT)   /* 3584 */
#define EMB   2048
#define NH    16
#define HD    128
#define MROWS (BSZ * TGT)     /* 2048 */
#define SLOT  (EMB * EMB)     /* 4M u32 per matrix */
#define QSCALE 0.08838834764831845f  /* 128^-0.5 */

/* scratch (static device arrays: allocation-free per harness rules) */
__device__ float g_q[MROWS * EMB];
__device__ float g_k[MROWS * EMB];
__device__ float g_v[MROWS * EMB];
/* permuted tf32 operands: 0=x(A) 1=wq(B) 2=wk(B) 3=wv(B) 4=wo(B) 5=attn(A) */
__device__ unsigned g_p[6 * SLOT];
/* permuted tf32 KV cache, fragment layout, per (b,h): 131072 uint4 */
__device__ uint4 g_kp[64 * 131072];
__device__ uint4 g_vp[64 * 131072];

/* ---------------- helpers ---------------- */
__device__ __forceinline__ unsigned f2tf(float f) {
    unsigned u;
    asm("cvt.rna.tf32.f32 %0, %1;" : "=r"(u) : "f"(f));
    return u;
}
__device__ __forceinline__ void mma4(float c[4], const uint4& a, unsigned b0, unsigned b1) {
    asm("mma.sync.aligned.m16n8k8.row.col.f32.tf32.tf32.f32 "
        "{%0,%1,%2,%3},{%4,%5,%6,%7},{%8,%9},{%0,%1,%2,%3};"
        : "+f"(c[0]), "+f"(c[1]), "+f"(c[2]), "+f"(c[3])
        : "r"(a.x), "r"(a.y), "r"(a.z), "r"(a.w), "r"(b0), "r"(b1));
}
__device__ __forceinline__ unsigned sm_u32(const void* p) {
    return (unsigned)__cvta_generic_to_shared(p);
}
__device__ __forceinline__ void cp16(unsigned dst, const void* src) {
    asm volatile("cp.async.cg.shared.global [%0], [%1], 16;" :: "r"(dst), "l"(src));
}
#define CP_COMMIT() asm volatile("cp.async.commit_group;")
#define CP_WAIT(n)  asm volatile("cp.async.wait_group %0;" :: "n"(n))
#define BAR_PAIR(id) asm volatile("bar.sync %0, 64;" :: "r"(id) : "memory")

/* ---------------- dense-operand permute (A/B fragment layouts) ---------------- */
__device__ __forceinline__ void permute_one(const float* __restrict__ src,
                                            uint4* __restrict__ dst,
                                            unsigned gid, int btype)
{
    unsigned lane = gid & 31, KSL = (gid >> 5) & 255, MI = gid >> 13;
    unsigned g = lane >> 2, tg = lane & 3;
    const float* p = src + (size_t)(MI * 16 + g) * EMB + KSL * 8 + tg;
    float v0 = p[0], v1 = p[8 * EMB], v2 = p[4], v3 = p[8 * EMB + 4];
    uint4 u;
    if (btype) { u.x = f2tf(v0); u.y = f2tf(v2); u.z = f2tf(v1); u.w = f2tf(v3); }
    else       { u.x = f2tf(v0); u.y = f2tf(v1); u.z = f2tf(v2); u.w = f2tf(v3); }
    dst[gid] = u;
}

__global__ void __launch_bounds__(256) convert5_kernel(
    const float* __restrict__ x,  const float* __restrict__ wq,
    const float* __restrict__ wk, const float* __restrict__ wv,
    const float* __restrict__ wo)
{
    int slot = blockIdx.y;
    const float* src = (slot == 0) ? x : (slot == 1) ? wq :
                       (slot == 2) ? wk : (slot == 3) ? wv : wo;
    unsigned gid = blockIdx.x * 256 + threadIdx.x;
    permute_one(src, (uint4*)(g_p + (size_t)slot * SLOT), gid, slot != 0);
}

/* ---------------- KV tile permute helper (64 j-rows x 128 d, staged in smem) ---- */
__device__ __forceinline__ void kv_permute_tile(
    const float* __restrict__ src,   /* + row0*EMB + h*HD pre-applied */
    float* Ts, int tt, int bh, int isV, int tid)
{
    const int lane = tid & 31, g = lane >> 2, tg = lane & 3;
    __syncthreads();
    #pragma unroll
    for (int p = 0; p < 8; p++) {
        int idx = tid + p * 256;
        int r = idx >> 5, c4 = (idx & 31) << 2;
        *(float4*)&Ts[r * 132 + c4] = *(const float4*)(src + (size_t)r * EMB + c4);
    }
    __syncthreads();
    if (!isV) {
        uint4* dst = g_kp + (size_t)bh * 131072;
        #pragma unroll
        for (int p = 0; p < 8; p++) {
            int idx = tid + p * 256;
            int pi_l = idx >> 9, ksl = (idx >> 5) & 15;
            int j0 = pi_l * 16, c = ksl * 8 + tg;
            uint4 u;
            u.x = f2tf(Ts[(j0 + g) * 132 + c]);
            u.y = f2tf(Ts[(j0 + g) * 132 + c + 4]);
            u.z = f2tf(Ts[(j0 + g + 8) * 132 + c]);
            u.w = f2tf(Ts[(j0 + g + 8) * 132 + c + 4]);
            dst[(size_t)(tt * 4 + pi_l) * 512 + ksl * 32 + lane] = u;
        }
    } else {
        uint4* dst = g_vp + (size_t)bh * 131072;
        #pragma unroll
        for (int p = 0; p < 8; p++) {
            int idx = tid + p * 256;
            int pi_d = idx >> 8, kslj = (idx >> 5) & 7;
            int d0 = pi_d * 16, j0 = kslj * 8;
            uint4 u;
            u.x = f2tf(Ts[(j0 + tg) * 132 + d0 + g]);
            u.y = f2tf(Ts[(j0 + tg + 4) * 132 + d0 + g]);
            u.z = f2tf(Ts[(j0 + tg) * 132 + d0 + g + 8]);
            u.w = f2tf(Ts[(j0 + tg + 4) * 132 + d0 + g + 8]);
            dst[(size_t)pi_d * 16384 + (size_t)(tt * 8 + kslj) * 32 + lane] = u;
        }
    }
}

/* permute NEW kv region (from g_k/g_v). 1024 blocks. */
__global__ void __launch_bounds__(256) permute_new_kernel()
{
    __shared__ float Ts[64 * 132];
    int job = blockIdx.x;               /* 0..1023 */
    int isV = job >= 512;
    int jj = job & 511;
    int bh = jj >> 3, tl = jj & 7;
    int b = bh >> 4, h = bh & 15;
    const float* src = (isV ? g_v : g_k) + ((size_t)(b * TGT) + tl * 64) * EMB + h * HD;
    kv_permute_tile(src, Ts, 56 + tl, bh, isV, threadIdx.x);
}

/* ---------------- dense GEMM: C[128,128] = A @ B^T, pre-permuted tf32 ---------------- */
#define GSTG 2048   /* uint4 per stage */
#define GEMM_SMEM (3 * GSTG * 16)

__device__ __forceinline__ void gemm_main(
    const uint4* __restrict__ Ag, const uint4* __restrict__ Bg,
    float c[4][4][4], uint4* S, int tid)
{
    const int lane = tid & 31, wid = tid >> 5;
    const int wm = wid >> 2, wn = wid & 3;

    for (int st = 0; st < 2; st++) {
        for (int i = 0; i < 8; i++) {
            int ch = tid + i * 256;
            int half = ch >> 10, cc = ch & 1023;
            int mi = cc >> 7, rest = cc & 127;
            const uint4* src = (half ? Bg : Ag) + (size_t)mi * 8192 + st * 128 + rest;
            cp16(sm_u32(S + st * GSTG + half * 1024 + cc), src);
        }
        CP_COMMIT();
    }

    for (int kt = 0; kt < 64; kt++) {
        if (kt < 63) CP_WAIT(1); else CP_WAIT(0);
        __syncthreads();

        if (kt + 2 < 64) {
            int st = (kt + 2) % 3;
            for (int i = 0; i < 8; i++) {
                int ch = tid + i * 256;
                int half = ch >> 10, cc = ch & 1023;
                int mi = cc >> 7, rest = cc & 127;
                const uint4* src = (half ? Bg : Ag) + (size_t)mi * 8192 + (kt + 2) * 128 + rest;
                cp16(sm_u32(S + st * GSTG + half * 1024 + cc), src);
            }
            CP_COMMIT();
        }

        const uint4* Af = S + (kt % 3) * GSTG;
        const uint4* Bf = Af + 1024;
        #pragma unroll
        for (int ks = 0; ks < 4; ks++) {
            uint4 a[4], bu[2];
            #pragma unroll
            for (int mt = 0; mt < 4; mt++)
                a[mt] = Af[((wm * 4 + mt) * 4 + ks) * 32 + lane];
            #pragma unroll
            for (int p = 0; p < 2; p++)
                bu[p] = Bf[((wn * 2 + p) * 4 + ks) * 32 + lane];
            #pragma unroll
            for (int mt = 0; mt < 4; mt++) {
                mma4(c[mt][0], a[mt], bu[0].x, bu[0].y);
                mma4(c[mt][1], a[mt], bu[0].z, bu[0].w);
                mma4(c[mt][2], a[mt], bu[1].x, bu[1].y);
                mma4(c[mt][3], a[mt], bu[1].z, bu[1].w);
            }
        }
    }
}

/* Fused QKV + interleaved old-KV permute plane.
   grid (96,16): x<48 -> gemm (sel = x>>4, nblk = x&15); x>=48 -> permute jobs. */
__global__ void __launch_bounds__(256, 2) qkv_kernel(
    const float* __restrict__ kc_in, const float* __restrict__ vc_in,
    const float* __restrict__ bq, const float* __restrict__ bk,
    const float* __restrict__ bv,
    float* __restrict__ okc, float* __restrict__ ovc, int write_cache)
{
    extern __shared__ uint4 S[];
    const int tid = threadIdx.x;

    if (blockIdx.x >= 48) {
        float* Ts = (float*)S;
        int pbid = (blockIdx.x - 48) + 48 * blockIdx.y;
        for (int job = pbid; job < 7168; job += 768) {
            int isV = job >= 3584;
            int jj = isV ? job - 3584 : job;
            int bh = jj / 56, tt = jj % 56;
            int b = bh >> 4, h = bh & 15;
            const float* src = (isV ? vc_in : kc_in)
                + ((size_t)(b * KVLEN) + tt * 64) * EMB + h * HD;
            kv_permute_tile(src, Ts, tt, bh, isV, tid);
        }
        return;
    }

    const int lane = tid & 31, wid = tid >> 5;
    const int g = lane >> 2, tg = lane & 3;
    const int wm = wid >> 2, wn = wid & 3;
    const int nb = blockIdx.x, mb = blockIdx.y;
    const int sel = nb >> 4, nblk = nb & 15;
    const float* bias = (sel == 0) ? bq : (sel == 1) ? bk : bv;

    const uint4* Ag = (const uint4*)(g_p) + (size_t)(mb * 8) * 8192;
    const uint4* Bg = (const uint4*)(g_p + (size_t)(1 + sel) * SLOT) + (size_t)(nblk * 8) * 8192;

    float c[4][4][4] = {};
    gemm_main(Ag, Bg, c, S, tid);

    #pragma unroll
    for (int mt = 0; mt < 4; mt++) {
        #pragma unroll
        for (int nt = 0; nt < 4; nt++) {
            int col = nblk * 128 + wn * 32 + nt * 8 + 2 * tg;
            #pragma unroll
            for (int half = 0; half < 2; half++) {
                int m = mb * 128 + wm * 64 + mt * 16 + g + half * 8;
                float v0 = c[mt][nt][half * 2 + 0] + bias[col];
                float v1 = c[mt][nt][half * 2 + 1] + bias[col + 1];
                if (sel == 0) {
                    g_q[(size_t)m * EMB + col]     = v0 * QSCALE;
                    g_q[(size_t)m * EMB + col + 1] = v1 * QSCALE;
                } else {
                    float* dst = (sel == 1) ? g_k : g_v;
                    dst[(size_t)m * EMB + col]     = v0;
                    dst[(size_t)m * EMB + col + 1] = v1;
                    if (write_cache) {
                        int bidx = m >> 9, t = m & 511;
                        float* cd = (sel == 1) ? okc : ovc;
                        size_t o = ((size_t)bidx * KVLEN + KVOLD + t) * EMB + col;
                        cd[o] = v0; cd[o + 1] = v1;
                    }
                }
            }
        }
    }
}

/* Output projection: grid (16,16). A = permuted attn (slot 5). */
__global__ void __launch_bounds__(256, 2) proj_kernel(
    const float* __restrict__ bo, float* __restrict__ out)
{
    extern __shared__ uint4 S[];
    const int tid = threadIdx.x;
    const int lane = tid & 31, wid = tid >> 5;
    const int g = lane >> 2, tg = lane & 3;
    const int wm = wid >> 2, wn = wid & 3;
    const int nblk = blockIdx.x, mb = blockIdx.y;

    const uint4* Ag = (const uint4*)(g_p + 5 * (size_t)SLOT) + (size_t)(mb * 8) * 8192;
    const uint4* Bg = (const uint4*)(g_p + 4 * (size_t)SLOT) + (size_t)(nblk * 8) * 8192;

    float c[4][4][4] = {};
    gemm_main(Ag, Bg, c, S, tid);

    #pragma unroll
    for (int mt = 0; mt < 4; mt++)
        #pragma unroll
        for (int nt = 0; nt < 4; nt++) {
            int col = nblk * 128 + wn * 32 + nt * 8 + 2 * tg;
            #pragma unroll
            for (int half = 0; half < 2; half++) {
                int m = mb * 128 + wm * 64 + mt * 16 + g + half * 8;
                out[(size_t)m * EMB + col]     = c[mt][nt][half * 2 + 0] + bo[col];
                out[(size_t)m * EMB + col + 1] = c[mt][nt][half * 2 + 1] + bo[col + 1];
            }
        }
}

/* ---------------- flash attention: 2 CTAs/SM, Q tile 64 ----------------
   256 thr, 8 warps: wm = wid>>1 (4 row-groups of 16), wn = wid&1.
   S warp-tile m16n32, PV m16n64. K and V single-buffered (partner CTA
   hides the load latency). smem (uint4):
     Qp[0..2047] | Kc[2048..4095] | Vc[4096..6143] | Pp[6144..7167]
   = 7168 uint4 = 114688 B -> 2 CTAs/SM. Regs capped at 128.
   blockIdx.z == BSZ -> cache-copier blocks (128 of them). */
#define OQ2 0
#define OK2 2048
#define OV2 4096
#define OP2 6144
#define ATT_SMEM (7168 * 16)
#define NT (KVLEN / 64)

__global__ void __launch_bounds__(256, 2) attn_kernel(
    const float* __restrict__ kc_in, const float* __restrict__ vc_in,
    const float* __restrict__ mask,
    float* __restrict__ okc, float* __restrict__ ovc, int write_cache)
{
    if (blockIdx.z == BSZ) {
        if (write_cache) {
            const int cb = blockIdx.x + gridDim.x * blockIdx.y;   /* 0..127 */
            const int N4 = KVOLD * EMB / 4;
            #pragma unroll 1
            for (int b = 0; b < BSZ; b++) {
                const float4* sk = (const float4*)(kc_in + (size_t)b * KVLEN * EMB);
                const float4* sv = (const float4*)(vc_in + (size_t)b * KVLEN * EMB);
                float4* dk = (float4*)(okc + (size_t)b * KVLEN * EMB);
                float4* dv = (float4*)(ovc + (size_t)b * KVLEN * EMB);
                for (int i = cb * 256 + (int)threadIdx.x; i < N4; i += 128 * 256) {
                    dk[i] = sk[i];
                    dv[i] = sv[i];
                }
            }
        }
        return;
    }

    extern __shared__ uint4 smq[];
    uint4* Qp = smq + OQ2;
    uint4* Kc = smq + OK2;
    uint4* Vc = smq + OV2;
    uint4* Pp = smq + OP2;
    __shared__ float pmax[2][64], psum[2][64];

    const int tid  = threadIdx.x;
    const int lane = tid & 31, wid = tid >> 5;
    const int g = lane >> 2, tg = lane & 3;
    const int wm = wid >> 1, wn = wid & 1;
    const int qt = blockIdx.x, h = blockIdx.y, b = blockIdx.z;

    const uint4* gK = g_kp + (size_t)(b * 16 + h) * 131072;
    const uint4* gV = g_vp + (size_t)(b * 16 + h) * 131072;
    const float* mbase = mask + (size_t)(qt * 64) * KVLEN;

    const int R0 = wm * 16 + g;       /* this thread's two rows */
    const int R1 = R0 + 8;

    /* prologue: K(0), V(0) */
    #pragma unroll
    for (int p = 0; p < 8; p++) {
        int idx = tid + p * 256;
        cp16(sm_u32(Kc + idx), gK + idx);
        cp16(sm_u32(Vc + idx), gV + (size_t)(idx >> 8) * 16384 + (idx & 255));
    }
    CP_COMMIT();

    /* Q load + permute: 64 groups (4 MI x 16 ksl), warp owns 8 */
    {
        const float* qb = g_q + (size_t)(b * TGT + qt * 64) * EMB + h * HD;
        #pragma unroll
        for (int q = 0; q < 8; q++) {
            int G = wid * 8 + q;
            int mi = G >> 4, ksl = G & 15;
            const float* p = qb + (size_t)(mi * 16 + g) * EMB + ksl * 8 + tg;
            uint4 u;
            u.x = f2tf(p[0]); u.y = f2tf(p[8 * EMB]);
            u.z = f2tf(p[4]); u.w = f2tf(p[8 * EMB + 4]);
            Qp[G * 32 + lane] = u;
        }
    }

    float m0 = -1e30f, m1 = -1e30f, l0 = 0.f, l1 = 0.f;
    float o[8][4] = {};

    #pragma unroll 1
    for (int t = 0; t < NT; t++) {
        /* mask prefetch (global latency overlaps the cp wait) */
        float2 mA[4], mB[4];
        #pragma unroll
        for (int j = 0; j < 4; j++) {
            int col = t * 64 + wn * 32 + j * 8 + 2 * tg;
            mA[j] = *(const float2*)(mbase + (size_t)R0 * KVLEN + col);
            mB[j] = *(const float2*)(mbase + (size_t)R1 * KVLEN + col);
        }

        CP_WAIT(0);
        __syncthreads();          /* K(t), V(t) visible everywhere */

        /* S = Q K^T : warp m16 x n32 */
        float s[4][4] = {};
        #pragma unroll
        for (int ks = 0; ks < 16; ks++) {
            uint4 a  = Qp[(wm * 16 + ks) * 32 + lane];
            uint4 b0 = Kc[((2 * wn) * 16 + ks) * 32 + lane];
            uint4 b1 = Kc[((2 * wn + 1) * 16 + ks) * 32 + lane];
            mma4(s[0], a, b0.x, b0.y);
            mma4(s[1], a, b0.z, b0.w);
            mma4(s[2], a, b1.x, b1.y);
            mma4(s[3], a, b1.z, b1.w);
        }

        /* + mask, row max */
        float mx0 = -1e30f, mx1 = -1e30f;
        #pragma unroll
        for (int j = 0; j < 4; j++) {
            s[j][0] += mA[j].x; s[j][1] += mA[j].y;
            s[j][2] += mB[j].x; s[j][3] += mB[j].y;
            mx0 = fmaxf(mx0, fmaxf(s[j][0], s[j][1]));
            mx1 = fmaxf(mx1, fmaxf(s[j][2], s[j][3]));
        }
        mx0 = fmaxf(mx0, __shfl_xor_sync(0xffffffffu, mx0, 1));
        mx0 = fmaxf(mx0, __shfl_xor_sync(0xffffffffu, mx0, 2));
        mx1 = fmaxf(mx1, __shfl_xor_sync(0xffffffffu, mx1, 1));
        mx1 = fmaxf(mx1, __shfl_xor_sync(0xffffffffu, mx1, 2));
        if (tg == 0) { pmax[wn][R0] = mx0; pmax[wn][R1] = mx1; }
        BAR_PAIR(1 + wm);

        float mn0 = fmaxf(m0, fmaxf(pmax[0][R0], pmax[1][R0]));
        float mn1 = fmaxf(m1, fmaxf(pmax[0][R1], pmax[1][R1]));
        float s0s = 0.f, s1s = 0.f;
        unsigned* Pu = (unsigned*)Pp;
        const int pbase = (wm * 8 + wn * 4) * 128;
        const int eoff = (g * 4 + (tg & 1) * 2) * 4 + (tg >> 1) * 2;
        #pragma unroll
        for (int j = 0; j < 4; j++) {
            s[j][0] = __expf(s[j][0] - mn0);
            s[j][1] = __expf(s[j][1] - mn0);
            s[j][2] = __expf(s[j][2] - mn1);
            s[j][3] = __expf(s[j][3] - mn1);
            s0s += s[j][0] + s[j][1];
            s1s += s[j][2] + s[j][3];
            int bb = pbase + j * 128 + eoff;
            Pu[bb + 0] = f2tf(s[j][0]);
            Pu[bb + 4] = f2tf(s[j][1]);
            Pu[bb + 1] = f2tf(s[j][2]);
            Pu[bb + 5] = f2tf(s[j][3]);
        }
        s0s += __shfl_xor_sync(0xffffffffu, s0s, 1);
        s0s += __shfl_xor_sync(0xffffffffu, s0s, 2);
        s1s += __shfl_xor_sync(0xffffffffu, s1s, 1);
        s1s += __shfl_xor_sync(0xffffffffu, s1s, 2);
        if (tg == 0) { psum[wn][R0] = s0s; psum[wn][R1] = s1s; }
        BAR_PAIR(1 + wm);

        float sc0 = __expf(m0 - mn0), sc1 = __expf(m1 - mn1);
        l0 = l0 * sc0 + psum[0][R0] + psum[1][R0];
        l1 = l1 * sc1 + psum[0][R1] + psum[1][R1];
        m0 = mn0; m1 = mn1;
        #pragma unroll
        for (int j2 = 0; j2 < 8; j2++) {
            o[j2][0] *= sc0; o[j2][1] *= sc0;
            o[j2][2] *= sc1; o[j2][3] *= sc1;
        }

        /* O += P V : warp m16 x n64 (d half by wn) */
        #pragma unroll
        for (int ks = 0; ks < 8; ks++) {
            uint4 a = Pp[(wm * 8 + ks) * 32 + lane];
            #pragma unroll
            for (int p = 0; p < 4; p++) {
                uint4 v = Vc[((4 * wn + p) * 8 + ks) * 32 + lane];
                mma4(o[2 * p],     a, v.x, v.y);
                mma4(o[2 * p + 1], a, v.z, v.w);
            }
        }

        __syncthreads();          /* all K/V/Pp reads of tile t done */
        if (t + 1 < NT) {         /* refill single buffers for t+1 */
            #pragma unroll
            for (int p = 0; p < 8; p++) {
                int idx = tid + p * 256;
                cp16(sm_u32(Kc + idx), gK + (size_t)(t + 1) * 2048 + idx);
                cp16(sm_u32(Vc + idx),
                     gV + (size_t)(idx >> 8) * 16384 + (t + 1) * 256 + (idx & 255));
            }
            CP_COMMIT();
        }
    }

    /* fused epilogue: normalize, stage, write permuted A-frags to g_p slot 5 */
    float* St = (float*)(smq + OK2);   /* 64 x 132 floats = 33 KB in K/V region */
    {
        float inv0 = 1.f / l0, inv1 = 1.f / l1;
        #pragma unroll
        for (int j2 = 0; j2 < 8; j2++) {
            int c = wn * 64 + j2 * 8 + 2 * tg;
            St[R0 * 132 + c]     = o[j2][0] * inv0;
            St[R0 * 132 + c + 1] = o[j2][1] * inv0;
            St[R1 * 132 + c]     = o[j2][2] * inv1;
            St[R1 * 132 + c + 1] = o[j2][3] * inv1;
        }
    }
    __syncthreads();
    {
        uint4* gp5 = (uint4*)(g_p + 5 * (size_t)SLOT);
        const int gMIb = b * 32 + qt * 4;   /* (b*TGT + qt*64)/16 */
        #pragma unroll
        for (int kk = 0; kk < 2; kk++) {
            int ksl = wid + kk * 8;
            #pragma unroll
            for (int MI = 0; MI < 4; MI++) {
                int r = MI * 16 + g, c = ksl * 8 + tg;
                uint4 u;
                u.x = f2tf(St[r * 132 + c]);
                u.y = f2tf(St[(r + 8) * 132 + c]);
                u.z = f2tf(St[r * 132 + c + 4]);
                u.w = f2tf(St[(r + 8) * 132 + c + 4]);
                gp5[((size_t)(gMIb + MI) * 256 + (h * 16 + ksl)) * 32 + lane] = u;
            }
        }
    }
}

/* ------------------------------------------------------------------ */
extern "C" void kernel_launch(void* const* d_in, const int* in_sizes, int n_in,
                              void* d_out, int out_size)
{
    const float* x       = (const float*)d_in[0];
    const float* k_cache = (const float*)d_in[1];
    const float* v_cache = (const float*)d_in[2];
    const float* mask    = (const float*)d_in[3];
    const float* wq = (const float*)d_in[4];
    const float* bq = (const float*)d_in[5];
    const float* wk = (const float*)d_in[6];
    const float* bk = (const float*)d_in[7];
    const float* wv = (const float*)d_in[8];
    const float* bv = (const float*)d_in[9];
    const float* wo = (const float*)d_in[10];
    const float* bo = (const float*)d_in[11];

    float* out = (float*)d_out;
    long long need = (long long)MROWS * EMB + 2LL * BSZ * KVLEN * EMB;
    int write_cache = ((long long)out_size >= need) ? 1 : 0;
    float* okc = out + (size_t)MROWS * EMB;
    float* ovc = okc + (size_t)BSZ * KVLEN * EMB;

    cudaFuncSetAttribute(attn_kernel,
                         cudaFuncAttributeMaxDynamicSharedMemorySize, ATT_SMEM);
    cudaFuncSetAttribute(qkv_kernel,
                         cudaFuncAttributeMaxDynamicSharedMemorySize, GEMM_SMEM);
    cudaFuncSetAttribute(proj_kernel,
                         cudaFuncAttributeMaxDynamicSharedMemorySize, GEMM_SMEM);

    convert5_kernel<<<dim3(4096, 5), 256>>>(x, wq, wk, wv, wo);
    qkv_kernel<<<dim3(96, 16), 256, GEMM_SMEM>>>(k_cache, v_cache,
                                                 bq, bk, bv, okc, ovc, write_cache);
    permute_new_kernel<<<1024, 256>>>();
    attn_kernel<<<dim3(8, 16, BSZ + 1), 256, ATT_SMEM>>>(k_cache, v_cache, mask,
                                                         okc, ovc, write_cache);
    proj_kernel<<<dim3(16, 16), 256, GEMM_SMEM>>>(bo, out);
}

// round 13
// speedup vs baseline: 1.6402x; 1.6402x over previous
#include <cuda_runtime.h>
#include <cuda_fp16.h>

#define BSZ   4
#define TGT   512
#define KVLEN 4096
#define KVOLD (KVLEN - TGT)   /* 3584 */
#define EMB   2048
#define NH    16
#define HD    128
#define MROWS (BSZ * TGT)     /* 2048 */
#define SLOT_H 524288         /* uint4 per fp16-permuted 2048x2048 matrix */
#define QSCALE 0.08838834764831845f  /* 128^-0.5 */

/* scratch (static device arrays: allocation-free per harness rules) */
__device__ float g_q[MROWS * EMB];
__device__ float g_k[MROWS * EMB];
__device__ float g_v[MROWS * EMB];
/* permuted fp16 operands: 0=x(A) 1=wq(B) 2=wk(B) 3=wv(B) 4=wo(B) 5=attn(A) */
__device__ uint4 g_p[6 * SLOT_H];                /* 48 MB */
/* permuted fp16 KV cache, fragment layout, per (b,h): 65536 uint4 */
__device__ uint4 g_kp[64 * 65536];               /* 64 MB */
__device__ uint4 g_vp[64 * 65536];               /* 64 MB */

/* ---------------- helpers ---------------- */
__device__ __forceinline__ unsigned h2u(float lo, float hi) {
    unsigned u;
    asm("cvt.rn.f16x2.f32 %0, %1, %2;" : "=r"(u) : "f"(hi), "f"(lo));
    return u;
}
__device__ __forceinline__ void mma8(float c[4], const uint4& a, unsigned b0, unsigned b1) {
    asm("mma.sync.aligned.m16n8k16.row.col.f32.f16.f16.f32 "
        "{%0,%1,%2,%3},{%4,%5,%6,%7},{%8,%9},{%0,%1,%2,%3};"
        : "+f"(c[0]), "+f"(c[1]), "+f"(c[2]), "+f"(c[3])
        : "r"(a.x), "r"(a.y), "r"(a.z), "r"(a.w), "r"(b0), "r"(b1));
}
__device__ __forceinline__ unsigned sm_u32(const void* p) {
    return (unsigned)__cvta_generic_to_shared(p);
}
__device__ __forceinline__ void cp16(unsigned dst, const void* src) {
    asm volatile("cp.async.cg.shared.global [%0], [%1], 16;" :: "r"(dst), "l"(src));
}
#define CP_COMMIT() asm volatile("cp.async.commit_group;")
#define CP_WAIT(n)  asm volatile("cp.async.wait_group %0;" :: "n"(n))
#define BAR_PAIR(id) asm volatile("bar.sync %0, 64;" :: "r"(id) : "memory")

/* ---------------- dense-operand permute (fp16 A/B fragment layouts) ----------
   Group (MI = row/16, KS = col/16), lane = g*4+tg. uint4 per lane:
   A-type: {h2(A[r][c],A[r][c+1]), h2(A[r+8][c],..), h2(A[r][c+8],..), h2(A[r+8][c+8],..)}
   B-type: {h2(W[r][c],..), h2(W[r][c+8],..), h2(W[r+8][c],..), h2(W[r+8][c+8],..)}
   r = 16*MI+g, c = 16*KS+2*tg. dst[(MI*128 + KS)*32 + lane].                  */
__device__ __forceinline__ void permute_one(const float* __restrict__ src,
                                            uint4* __restrict__ dst,
                                            unsigned gid, int btype)
{
    unsigned lane = gid & 31, KS = (gid >> 5) & 127, MI = gid >> 12;
    unsigned g = lane >> 2, tg = lane & 3;
    const float* p = src + (size_t)(MI * 16 + g) * EMB + KS * 16 + 2 * tg;
    float2 v0 = *(const float2*)(p);
    float2 v1 = *(const float2*)(p + 8 * EMB);
    float2 v2 = *(const float2*)(p + 8);
    float2 v3 = *(const float2*)(p + 8 * EMB + 8);
    uint4 u;
    if (btype) {
        u.x = h2u(v0.x, v0.y); u.y = h2u(v2.x, v2.y);
        u.z = h2u(v1.x, v1.y); u.w = h2u(v3.x, v3.y);
    } else {
        u.x = h2u(v0.x, v0.y); u.y = h2u(v1.x, v1.y);
        u.z = h2u(v2.x, v2.y); u.w = h2u(v3.x, v3.y);
    }
    dst[gid] = u;
}

__global__ void __launch_bounds__(256) convert5_kernel(
    const float* __restrict__ x,  const float* __restrict__ wq,
    const float* __restrict__ wk, const float* __restrict__ wv,
    const float* __restrict__ wo)
{
    int slot = blockIdx.y;
    const float* src = (slot == 0) ? x : (slot == 1) ? wq :
                       (slot == 2) ? wk : (slot == 3) ? wv : wo;
    unsigned gid = blockIdx.x * 256 + threadIdx.x;
    permute_one(src, g_p + (size_t)slot * SLOT_H, gid, slot != 0);
}

/* ---------------- KV tile permute (64 j x 128 d staged in smem, fp16 out) ----
   K: B-type over [j][d]: groups (NI=j/16 [4], KS=d/16 [8]);
      per-bh layout [tile][NI][KS][lane], 1024 u4/tile.
   V: B-type over [d][j] (k=j): groups (NI=d/16 [8], KSj=j/16 [4]);
      per-bh layout [NI][tile*4+KSj][lane] (NI stride 8192 u4).               */
__device__ __forceinline__ void kv_permute_tile(
    const float* __restrict__ src, float* Ts, int tt, int bh, int isV, int tid)
{
    const int lane = tid & 31, g = lane >> 2, tg = lane & 3;
    __syncthreads();
    #pragma unroll
    for (int p = 0; p < 8; p++) {
        int idx = tid + p * 256;
        int r = idx >> 5, c4 = (idx & 31) << 2;
        *(float4*)&Ts[r * 132 + c4] = *(const float4*)(src + (size_t)r * EMB + c4);
    }
    __syncthreads();
    if (!isV) {
        uint4* dst = g_kp + (size_t)bh * 65536 + (size_t)tt * 1024;
        #pragma unroll
        for (int p = 0; p < 4; p++) {
            int idx = tid + p * 256;                 /* (NI*8+KS)*32+lane */
            int KS = (idx >> 5) & 7, NI = idx >> 8;
            int j = NI * 16 + g, d = KS * 16 + 2 * tg;
            uint4 u;
            u.x = h2u(Ts[j * 132 + d],           Ts[j * 132 + d + 1]);
            u.y = h2u(Ts[j * 132 + d + 8],       Ts[j * 132 + d + 9]);
            u.z = h2u(Ts[(j + 8) * 132 + d],     Ts[(j + 8) * 132 + d + 1]);
            u.w = h2u(Ts[(j + 8) * 132 + d + 8], Ts[(j + 8) * 132 + d + 9]);
            dst[idx] = u;
        }
    } else {
        uint4* dst = g_vp + (size_t)bh * 65536;
        #pragma unroll
        for (int p = 0; p < 4; p++) {
            int idx = tid + p * 256;                 /* NI*128 + KSj*32 + lane */
            int KSj = (idx >> 5) & 3, NI = idx >> 7;
            int j = KSj * 16 + 2 * tg, d = NI * 16 + g;
            uint4 u;
            u.x = h2u(Ts[j * 132 + d],           Ts[(j + 1) * 132 + d]);
            u.y = h2u(Ts[(j + 8) * 132 + d],     Ts[(j + 9) * 132 + d]);
            u.z = h2u(Ts[j * 132 + d + 8],       Ts[(j + 1) * 132 + d + 8]);
            u.w = h2u(Ts[(j + 8) * 132 + d + 8], Ts[(j + 9) * 132 + d + 8]);
            dst[(size_t)NI * 8192 + (tt * 4 + KSj) * 32 + (idx & 31)] = u;
        }
    }
}

/* permute NEW kv region (from g_k/g_v). 1024 blocks. */
__global__ void __launch_bounds__(256) permute_new_kernel()
{
    __shared__ float Ts[64 * 132];
    int job = blockIdx.x;
    int isV = job >= 512;
    int jj = job & 511;
    int bh = jj >> 3, tl = jj & 7;
    int b = bh >> 4, h = bh & 15;
    const float* src = (isV ? g_v : g_k) + ((size_t)(b * TGT) + tl * 64) * EMB + h * HD;
    kv_permute_tile(src, Ts, 56 + tl, bh, isV, threadIdx.x);
}

/* ---------------- dense GEMM: C[128,128] = A @ B^T, fp16 fragments ----------
   8 warps (2 wm x 4 wn), warp tile m64n32. k-chunk = 32 (2 KS16).
   Stage = 512 u4 A + 512 u4 B = 16 KB; 3 stages = 48 KB.                    */
#define GSTG 1024
#define GEMM_SMEM (3 * GSTG * 16)

__device__ __forceinline__ void gemm_main(
    const uint4* __restrict__ Ag, const uint4* __restrict__ Bg,
    float c[4][4][4], uint4* S, int tid)
{
    const int lane = tid & 31, wid = tid >> 5;
    const int wm = wid >> 2, wn = wid & 3;

    #pragma unroll
    for (int st = 0; st < 2; st++) {
        #pragma unroll
        for (int i = 0; i < 4; i++) {
            int ch = tid + i * 256;
            int half = ch >> 9, cc = ch & 511;
            int mi = cc >> 6, ksl = (cc >> 5) & 1, l = cc & 31;
            const uint4* src = (half ? Bg : Ag)
                + (size_t)mi * 4096 + (2 * st + ksl) * 32 + l;
            cp16(sm_u32(S + st * GSTG + half * 512 + cc), src);
        }
        CP_COMMIT();
    }

    for (int kt = 0; kt < 64; kt++) {
        if (kt < 63) CP_WAIT(1); else CP_WAIT(0);
        __syncthreads();

        if (kt + 2 < 64) {
            int st = (kt + 2) % 3;
            #pragma unroll
            for (int i = 0; i < 4; i++) {
                int ch = tid + i * 256;
                int half = ch >> 9, cc = ch & 511;
                int mi = cc >> 6, ksl = (cc >> 5) & 1, l = cc & 31;
                const uint4* src = (half ? Bg : Ag)
                    + (size_t)mi * 4096 + (2 * (kt + 2) + ksl) * 32 + l;
                cp16(sm_u32(S + st * GSTG + half * 512 + cc), src);
            }
            CP_COMMIT();
        }

        const uint4* Af = S + (kt % 3) * GSTG;
        const uint4* Bf = Af + 512;
        #pragma unroll
        for (int ks = 0; ks < 2; ks++) {
            uint4 a[4], bu[2];
            #pragma unroll
            for (int mt = 0; mt < 4; mt++)
                a[mt] = Af[((wm * 4 + mt) * 2 + ks) * 32 + lane];
            #pragma unroll
            for (int p = 0; p < 2; p++)
                bu[p] = Bf[((wn * 2 + p) * 2 + ks) * 32 + lane];
            #pragma unroll
            for (int mt = 0; mt < 4; mt++) {
                mma8(c[mt][0], a[mt], bu[0].x, bu[0].y);
                mma8(c[mt][1], a[mt], bu[0].z, bu[0].w);
                mma8(c[mt][2], a[mt], bu[1].x, bu[1].y);
                mma8(c[mt][3], a[mt], bu[1].z, bu[1].w);
            }
        }
    }
}

/* Fused QKV + interleaved old-KV permute plane. grid (96,16). */
__global__ void __launch_bounds__(256, 2) qkv_kernel(
    const float* __restrict__ kc_in, const float* __restrict__ vc_in,
    const float* __restrict__ bq, const float* __restrict__ bk,
    const float* __restrict__ bv,
    float* __restrict__ okc, float* __restrict__ ovc, int write_cache)
{
    extern __shared__ uint4 S[];
    const int tid = threadIdx.x;

    if (blockIdx.x >= 48) {
        float* Ts = (float*)S;
        int pbid = (blockIdx.x - 48) + 48 * blockIdx.y;
        for (int job = pbid; job < 7168; job += 768) {
            int isV = job >= 3584;
            int jj = isV ? job - 3584 : job;
            int bh = jj / 56, tt = jj % 56;
            int b = bh >> 4, h = bh & 15;
            const float* src = (isV ? vc_in : kc_in)
                + ((size_t)(b * KVLEN) + tt * 64) * EMB + h * HD;
            kv_permute_tile(src, Ts, tt, bh, isV, tid);
        }
        return;
    }

    const int lane = tid & 31, wid = tid >> 5;
    const int g = lane >> 2, tg = lane & 3;
    const int wm = wid >> 2, wn = wid & 3;
    const int nb = blockIdx.x, mb = blockIdx.y;
    const int sel = nb >> 4, nblk = nb & 15;
    const float* bias = (sel == 0) ? bq : (sel == 1) ? bk : bv;

    const uint4* Ag = g_p + (size_t)mb * 32768;
    const uint4* Bg = g_p + (size_t)(1 + sel) * SLOT_H + (size_t)nblk * 32768;

    float c[4][4][4] = {};
    gemm_main(Ag, Bg, c, S, tid);

    #pragma unroll
    for (int mt = 0; mt < 4; mt++) {
        #pragma unroll
        for (int nt = 0; nt < 4; nt++) {
            int col = nblk * 128 + wn * 32 + nt * 8 + 2 * tg;
            #pragma unroll
            for (int half = 0; half < 2; half++) {
                int m = mb * 128 + wm * 64 + mt * 16 + g + half * 8;
                float v0 = c[mt][nt][half * 2 + 0] + bias[col];
                float v1 = c[mt][nt][half * 2 + 1] + bias[col + 1];
                if (sel == 0) {
                    g_q[(size_t)m * EMB + col]     = v0 * QSCALE;
                    g_q[(size_t)m * EMB + col + 1] = v1 * QSCALE;
                } else {
                    float* dst = (sel == 1) ? g_k : g_v;
                    dst[(size_t)m * EMB + col]     = v0;
                    dst[(size_t)m * EMB + col + 1] = v1;
                    if (write_cache) {
                        int bidx = m >> 9, t = m & 511;
                        float* cd = (sel == 1) ? okc : ovc;
                        size_t o = ((size_t)bidx * KVLEN + KVOLD + t) * EMB + col;
                        cd[o] = v0; cd[o + 1] = v1;
                    }
                }
            }
        }
    }
}

/* Output projection: grid (16,16). A = fp16-permuted attn (slot 5). */
__global__ void __launch_bounds__(256, 2) proj_kernel(
    const float* __restrict__ bo, float* __restrict__ out)
{
    extern __shared__ uint4 S[];
    const int tid = threadIdx.x;
    const int lane = tid & 31, wid = tid >> 5;
    const int g = lane >> 2, tg = lane & 3;
    const int wm = wid >> 2, wn = wid & 3;
    const int nblk = blockIdx.x, mb = blockIdx.y;

    const uint4* Ag = g_p + 5 * (size_t)SLOT_H + (size_t)mb * 32768;
    const uint4* Bg = g_p + 4 * (size_t)SLOT_H + (size_t)nblk * 32768;

    float c[4][4][4] = {};
    gemm_main(Ag, Bg, c, S, tid);

    #pragma unroll
    for (int mt = 0; mt < 4; mt++)
        #pragma unroll
        for (int nt = 0; nt < 4; nt++) {
            int col = nblk * 128 + wn * 32 + nt * 8 + 2 * tg;
            #pragma unroll
            for (int half = 0; half < 2; half++) {
                int m = mb * 128 + wm * 64 + mt * 16 + g + half * 8;
                out[(size_t)m * EMB + col]     = c[mt][nt][half * 2 + 0] + bo[col];
                out[(size_t)m * EMB + col + 1] = c[mt][nt][half * 2 + 1] + bo[col + 1];
            }
        }
}

/* ---------------- flash attention: fp16, deferred-PV pipeline ----------------
   256 thr, 8 warps (4 wm x 2 wn). Q tile 128, KV tile 64.
   S m32n32 (k16 x 8), PV m32n64 (k16 x 4). smem (uint4):
   Qp[0..2047] | K 2x1024 | V 2x1024 | Pp[1024] = 7168 u4 = 114688 B.        */
#define OQ 0
#define OK 2048
#define OV 4096
#define OP 6144
#define ATT_SMEM (7168 * 16)
#define NT (KVLEN / 64)

__global__ void __launch_bounds__(256, 1) attn_kernel(
    const float* __restrict__ kc_in, const float* __restrict__ vc_in,
    const float* __restrict__ mask,
    float* __restrict__ okc, float* __restrict__ ovc, int write_cache)
{
    if (blockIdx.z == BSZ) {
        if (write_cache) {
            const int cb = blockIdx.x + gridDim.x * blockIdx.y;   /* 0..63 */
            const int N4 = KVOLD * EMB / 4;
            #pragma unroll 1
            for (int b = 0; b < BSZ; b++) {
                const float4* sk = (const float4*)(kc_in + (size_t)b * KVLEN * EMB);
                const float4* sv = (const float4*)(vc_in + (size_t)b * KVLEN * EMB);
                float4* dk = (float4*)(okc + (size_t)b * KVLEN * EMB);
                float4* dv = (float4*)(ovc + (size_t)b * KVLEN * EMB);
                for (int i = cb * 256 + (int)threadIdx.x; i < N4; i += 64 * 256) {
                    dk[i] = sk[i];
                    dv[i] = sv[i];
                }
            }
        }
        return;
    }

    extern __shared__ uint4 smq[];
    uint4* Qp = smq + OQ;
    uint4* Pp = smq + OP;
    __shared__ float pmax[2][128], psum[2][128];

    const int tid  = threadIdx.x;
    const int lane = tid & 31, wid = tid >> 5;
    const int g = lane >> 2, tg = lane & 3;
    const int wm = wid >> 1, wn = wid & 1;
    const int qt = blockIdx.x, h = blockIdx.y, b = blockIdx.z;

    const uint4* gK = g_kp + (size_t)(b * 16 + h) * 65536;
    const uint4* gV = g_vp + (size_t)(b * 16 + h) * 65536;
    const float* mbase = mask + (size_t)(qt * 128) * KVLEN;

    /* prologue: K(0) */
    #pragma unroll
    for (int p = 0; p < 4; p++) {
        int idx = tid + p * 256;
        cp16(sm_u32(smq + OK + idx), gK + idx);
    }
    CP_COMMIT();

    /* Q load + pack fp16 A-frags: 64 groups (MI 8 x ksl 8), warp owns 8 */
    {
        const float* qb = g_q + (size_t)(b * TGT + qt * 128) * EMB + h * HD;
        #pragma unroll
        for (int q = 0; q < 8; q++) {
            int G = wid * 8 + q;
            int mi = G >> 3, ksl = G & 7;
            const float* p = qb + (size_t)(mi * 16 + g) * EMB + ksl * 16 + 2 * tg;
            float2 v0 = *(const float2*)(p);
            float2 v1 = *(const float2*)(p + 8 * EMB);
            float2 v2 = *(const float2*)(p + 8);
            float2 v3 = *(const float2*)(p + 8 * EMB + 8);
            uint4 u;
            u.x = h2u(v0.x, v0.y); u.y = h2u(v1.x, v1.y);
            u.z = h2u(v2.x, v2.y); u.w = h2u(v3.x, v3.y);
            Qp[G * 32 + lane] = u;
        }
    }

    float m_[2][2], l_[2][2];
    #pragma unroll
    for (int i = 0; i < 2; i++)
        #pragma unroll
        for (int hh = 0; hh < 2; hh++) { m_[i][hh] = -1e30f; l_[i][hh] = 0.f; }
    float o[2][8][4] = {};

    #pragma unroll 1
    for (int t = 0; t < NT; t++) {
        /* mask prefetch */
        float2 mk[2][2][4];
        #pragma unroll
        for (int i = 0; i < 2; i++)
            #pragma unroll
            for (int hh = 0; hh < 2; hh++) {
                int r = wm * 32 + i * 16 + hh * 8 + g;
                #pragma unroll
                for (int j = 0; j < 4; j++)
                    mk[i][hh][j] = *(const float2*)(mbase + (size_t)r * KVLEN
                                                    + t * 64 + wn * 32 + j * 8 + 2 * tg);
            }

        CP_WAIT(0);          /* group(t-1): K(t) + V(t-1) ready */
        __syncthreads();

        /* issue group(t): K(t+1) -> slot (t+1)&1, V(t) -> slot t&1 */
        if (t + 1 < NT) {
            #pragma unroll
            for (int p = 0; p < 4; p++) {
                int idx = tid + p * 256;
                cp16(sm_u32(smq + OK + ((t + 1) & 1) * 1024 + idx),
                     gK + (size_t)(t + 1) * 1024 + idx);
            }
        }
        #pragma unroll
        for (int p = 0; p < 4; p++) {
            int idx = tid + p * 256;
            cp16(sm_u32(smq + OV + (t & 1) * 1024 + idx),
                 gV + (size_t)(idx >> 7) * 8192 + t * 128 + (idx & 127));
        }
        CP_COMMIT();

        const uint4* Kc = smq + OK + (t & 1) * 1024;

        /* S(t) = Q K^T : warp m32 x n32, 8 k16-slices */
        float s[2][4][4] = {};
        #pragma unroll
        for (int ks = 0; ks < 8; ks++) {
            uint4 a0 = Qp[((2 * wm) * 8 + ks) * 32 + lane];
            uint4 a1 = Qp[((2 * wm + 1) * 8 + ks) * 32 + lane];
            uint4 KA = Kc[((2 * wn) * 8 + ks) * 32 + lane];
            uint4 KB = Kc[((2 * wn + 1) * 8 + ks) * 32 + lane];
            mma8(s[0][0], a0, KA.x, KA.y); mma8(s[0][1], a0, KA.z, KA.w);
            mma8(s[0][2], a0, KB.x, KB.y); mma8(s[0][3], a0, KB.z, KB.w);
            mma8(s[1][0], a1, KA.x, KA.y); mma8(s[1][1], a1, KA.z, KA.w);
            mma8(s[1][2], a1, KB.x, KB.y); mma8(s[1][3], a1, KB.z, KB.w);
        }

        /* PV(t-1): queued behind S(t); drains under the softmax */
        if (t > 0) {
            const uint4* Vc = smq + OV + ((t & 1) ^ 1) * 1024;
            #pragma unroll
            for (int ks = 0; ks < 4; ks++) {
                uint4 a0 = Pp[((2 * wm) * 4 + ks) * 32 + lane];
                uint4 a1 = Pp[((2 * wm + 1) * 4 + ks) * 32 + lane];
                #pragma unroll
                for (int p = 0; p < 4; p++) {
                    uint4 v = Vc[((4 * wn + p) * 4 + ks) * 32 + lane];
                    mma8(o[0][2 * p],     a0, v.x, v.y);
                    mma8(o[0][2 * p + 1], a0, v.z, v.w);
                    mma8(o[1][2 * p],     a1, v.x, v.y);
                    mma8(o[1][2 * p + 1], a1, v.z, v.w);
                }
            }
        }

        /* softmax(t) */
        float mx[2][2];
        #pragma unroll
        for (int i = 0; i < 2; i++) {
            mx[i][0] = -1e30f; mx[i][1] = -1e30f;
            #pragma unroll
            for (int j = 0; j < 4; j++) {
                s[i][j][0] += mk[i][0][j].x; s[i][j][1] += mk[i][0][j].y;
                s[i][j][2] += mk[i][1][j].x; s[i][j][3] += mk[i][1][j].y;
                mx[i][0] = fmaxf(mx[i][0], fmaxf(s[i][j][0], s[i][j][1]));
                mx[i][1] = fmaxf(mx[i][1], fmaxf(s[i][j][2], s[i][j][3]));
            }
            mx[i][0] = fmaxf(mx[i][0], __shfl_xor_sync(0xffffffffu, mx[i][0], 1));
            mx[i][0] = fmaxf(mx[i][0], __shfl_xor_sync(0xffffffffu, mx[i][0], 2));
            mx[i][1] = fmaxf(mx[i][1], __shfl_xor_sync(0xffffffffu, mx[i][1], 1));
            mx[i][1] = fmaxf(mx[i][1], __shfl_xor_sync(0xffffffffu, mx[i][1], 2));
        }
        if (tg == 0) {
            #pragma unroll
            for (int i = 0; i < 2; i++) {
                pmax[wn][wm * 32 + i * 16 + g]     = mx[i][0];
                pmax[wn][wm * 32 + i * 16 + 8 + g] = mx[i][1];
            }
        }
        BAR_PAIR(1 + wm);

        float mn[2][2], ss[2][2];
        unsigned* Pu = (unsigned*)Pp;
        #pragma unroll
        for (int i = 0; i < 2; i++) {
            #pragma unroll
            for (int hh = 0; hh < 2; hh++) {
                int r = wm * 32 + i * 16 + hh * 8 + g;
                mn[i][hh] = fmaxf(m_[i][hh], fmaxf(pmax[0][r], pmax[1][r]));
                ss[i][hh] = 0.f;
            }
            #pragma unroll
            for (int j = 0; j < 4; j++) {
                s[i][j][0] = __expf(s[i][j][0] - mn[i][0]);
                s[i][j][1] = __expf(s[i][j][1] - mn[i][0]);
                s[i][j][2] = __expf(s[i][j][2] - mn[i][1]);
                s[i][j][3] = __expf(s[i][j][3] - mn[i][1]);
                ss[i][0] += s[i][j][0] + s[i][j][1];
                ss[i][1] += s[i][j][2] + s[i][j][3];
                /* P A-frag store: group G = (2wm+i)*4 + 2wn + (j>>1) */
                int G = (2 * wm + i) * 4 + 2 * wn + (j >> 1);
                int comp0 = (j & 1) ? 2 : 0;
                Pu[(G * 32 + lane) * 4 + comp0]     = h2u(s[i][j][0], s[i][j][1]);
                Pu[(G * 32 + lane) * 4 + comp0 + 1] = h2u(s[i][j][2], s[i][j][3]);
            }
            #pragma unroll
            for (int hh = 0; hh < 2; hh++) {
                ss[i][hh] += __shfl_xor_sync(0xffffffffu, ss[i][hh], 1);
                ss[i][hh] += __shfl_xor_sync(0xffffffffu, ss[i][hh], 2);
            }
        }
        if (tg == 0) {
            #pragma unroll
            for (int i = 0; i < 2; i++) {
                psum[wn][wm * 32 + i * 16 + g]     = ss[i][0];
                psum[wn][wm * 32 + i * 16 + 8 + g] = ss[i][1];
            }
        }
        BAR_PAIR(1 + wm);

        #pragma unroll
        for (int i = 0; i < 2; i++) {
            float sc[2];
            #pragma unroll
            for (int hh = 0; hh < 2; hh++) {
                int r = wm * 32 + i * 16 + hh * 8 + g;
                sc[hh] = __expf(m_[i][hh] - mn[i][hh]);
                l_[i][hh] = l_[i][hh] * sc[hh] + psum[0][r] + psum[1][r];
                m_[i][hh] = mn[i][hh];
            }
            #pragma unroll
            for (int j2 = 0; j2 < 8; j2++) {
                o[i][j2][0] *= sc[0]; o[i][j2][1] *= sc[0];
                o[i][j2][2] *= sc[1]; o[i][j2][3] *= sc[1];
            }
        }
    }

    /* drain: PV(NT-1) */
    CP_WAIT(0);
    __syncthreads();
    {
        const uint4* Vc = smq + OV + ((NT - 1) & 1) * 1024;
        #pragma unroll
        for (int ks = 0; ks < 4; ks++) {
            uint4 a0 = Pp[((2 * wm) * 4 + ks) * 32 + lane];
            uint4 a1 = Pp[((2 * wm + 1) * 4 + ks) * 32 + lane];
            #pragma unroll
            for (int p = 0; p < 4; p++) {
                uint4 v = Vc[((4 * wn + p) * 4 + ks) * 32 + lane];
                mma8(o[0][2 * p],     a0, v.x, v.y);
                mma8(o[0][2 * p + 1], a0, v.z, v.w);
                mma8(o[1][2 * p],     a1, v.x, v.y);
                mma8(o[1][2 * p + 1], a1, v.z, v.w);
            }
        }
    }

    /* fused epilogue: normalize, stage f32, write fp16 A-frags to slot 5 */
    __syncthreads();
    float* St = (float*)smq;   /* 128 x 132 floats = 67.6 KB over Qp/K/V */
    #pragma unroll
    for (int i = 0; i < 2; i++) {
        float inv0 = 1.f / l_[i][0], inv1 = 1.f / l_[i][1];
        int rA = wm * 32 + i * 16 + g;
        int rB = rA + 8;
        #pragma unroll
        for (int j2 = 0; j2 < 8; j2++) {
            int c = wn * 64 + j2 * 8 + 2 * tg;
            St[rA * 132 + c]     = o[i][j2][0] * inv0;
            St[rA * 132 + c + 1] = o[i][j2][1] * inv0;
            St[rB * 132 + c]     = o[i][j2][2] * inv1;
            St[rB * 132 + c + 1] = o[i][j2][3] * inv1;
        }
    }
    __syncthreads();
    {
        uint4* gp5 = g_p + 5 * (size_t)SLOT_H;
        const int gMIb = b * 32 + qt * 8;
        #pragma unroll
        for (int MI = 0; MI < 8; MI++) {
            int r = MI * 16 + g, c = wid * 16 + 2 * tg;
            uint4 u;
            u.x = h2u(St[r * 132 + c],           St[r * 132 + c + 1]);
            u.y = h2u(St[(r + 8) * 132 + c],     St[(r + 8) * 132 + c + 1]);
            u.z = h2u(St[r * 132 + c + 8],       St[r * 132 + c + 9]);
            u.w = h2u(St[(r + 8) * 132 + c + 8], St[(r + 8) * 132 + c + 9]);
            gp5[((size_t)(gMIb + MI) * 128 + (h * 8 + wid)) * 32 + lane] = u;
        }
    }
}

/* ------------------------------------------------------------------ */
extern "C" void kernel_launch(void* const* d_in, const int* in_sizes, int n_in,
                              void* d_out, int out_size)
{
    const float* x       = (const float*)d_in[0];
    const float* k_cache = (const float*)d_in[1];
    const float* v_cache = (const float*)d_in[2];
    const float* mask    = (const float*)d_in[3];
    const float* wq = (const float*)d_in[4];
    const float* bq = (const float*)d_in[5];
    const float* wk = (const float*)d_in[6];
    const float* bk = (const float*)d_in[7];
    const float* wv = (const float*)d_in[8];
    const float* bv = (const float*)d_in[9];
    const float* wo = (const float*)d_in[10];
    const float* bo = (const float*)d_in[11];

    float* out = (float*)d_out;
    long long need = (long long)MROWS * EMB + 2LL * BSZ * KVLEN * EMB;
    int write_cache = ((long long)out_size >= need) ? 1 : 0;
    float* okc = out + (size_t)MROWS * EMB;
    float* ovc = okc + (size_t)BSZ * KVLEN * EMB;

    cudaFuncSetAttribute(attn_kernel,
                         cudaFuncAttributeMaxDynamicSharedMemorySize, ATT_SMEM);
    cudaFuncSetAttribute(qkv_kernel,
                         cudaFuncAttributeMaxDynamicSharedMemorySize, GEMM_SMEM);
    cudaFuncSetAttribute(proj_kernel,
                         cudaFuncAttributeMaxDynamicSharedMemorySize, GEMM_SMEM);

    convert5_kernel<<<dim3(2048, 5), 256>>>(x, wq, wk, wv, wo);
    qkv_kernel<<<dim3(96, 16), 256, GEMM_SMEM>>>(k_cache, v_cache,
                                                 bq, bk, bv, okc, ovc, write_cache);
    permute_new_kernel<<<1024, 256>>>();
    attn_kernel<<<dim3(4, 16, BSZ + 1), 256, ATT_SMEM>>>(k_cache, v_cache, mask,
                                                         okc, ovc, write_cache);
    proj_kernel<<<dim3(16, 16), 256, GEMM_SMEM>>>(bo, out);
}

// round 14
// speedup vs baseline: 1.7007x; 1.0369x over previous
#include <cuda_runtime.h>
#include <cuda_fp16.h>

#define BSZ   4
#define TGT   512
#define KVLEN 4096
#define KVOLD (KVLEN - TGT)   /* 3584 */
#define EMB   2048
#define NH    16
#define HD    128
#define MROWS (BSZ * TGT)     /* 2048 */
#define SLOT_H 524288         /* uint4 per fp16-permuted 2048x2048 matrix */
#define QSCALE 0.08838834764831845f  /* 128^-0.5 */

/* scratch (static device arrays: allocation-free per harness rules) */
__device__ float g_q[MROWS * EMB];
__device__ float g_k[MROWS * EMB];
__device__ float g_v[MROWS * EMB];
/* permuted fp16 operands: 0=x(A) 1=wq(B) 2=wk(B) 3=wv(B) 4=wo(B) 5=attn(A) */
__device__ uint4 g_p[6 * SLOT_H];                /* 48 MB */
/* permuted fp16 KV cache, fragment layout, per (b,h): 65536 uint4 */
__device__ uint4 g_kp[64 * 65536];               /* 64 MB */
__device__ uint4 g_vp[64 * 65536];               /* 64 MB */

/* ---------------- helpers ---------------- */
__device__ __forceinline__ unsigned h2u(float lo, float hi) {
    unsigned u;
    asm("cvt.rn.f16x2.f32 %0, %1, %2;" : "=r"(u) : "f"(hi), "f"(lo));
    return u;
}
__device__ __forceinline__ void mma8(float c[4], const uint4& a, unsigned b0, unsigned b1) {
    asm("mma.sync.aligned.m16n8k16.row.col.f32.f16.f16.f32 "
        "{%0,%1,%2,%3},{%4,%5,%6,%7},{%8,%9},{%0,%1,%2,%3};"
        : "+f"(c[0]), "+f"(c[1]), "+f"(c[2]), "+f"(c[3])
        : "r"(a.x), "r"(a.y), "r"(a.z), "r"(a.w), "r"(b0), "r"(b1));
}
__device__ __forceinline__ unsigned sm_u32(const void* p) {
    return (unsigned)__cvta_generic_to_shared(p);
}
__device__ __forceinline__ void cp16(unsigned dst, const void* src) {
    asm volatile("cp.async.cg.shared.global [%0], [%1], 16;" :: "r"(dst), "l"(src));
}
#define CP_COMMIT() asm volatile("cp.async.commit_group;")
#define CP_WAIT(n)  asm volatile("cp.async.wait_group %0;" :: "n"(n))

/* ---------------- dense-operand permute (fp16 A/B fragment layouts) ---------- */
__device__ __forceinline__ void permute_one(const float* __restrict__ src,
                                            uint4* __restrict__ dst,
                                            unsigned gid, int btype)
{
    unsigned lane = gid & 31, KS = (gid >> 5) & 127, MI = gid >> 12;
    unsigned g = lane >> 2, tg = lane & 3;
    const float* p = src + (size_t)(MI * 16 + g) * EMB + KS * 16 + 2 * tg;
    float2 v0 = *(const float2*)(p);
    float2 v1 = *(const float2*)(p + 8 * EMB);
    float2 v2 = *(const float2*)(p + 8);
    float2 v3 = *(const float2*)(p + 8 * EMB + 8);
    uint4 u;
    if (btype) {
        u.x = h2u(v0.x, v0.y); u.y = h2u(v2.x, v2.y);
        u.z = h2u(v1.x, v1.y); u.w = h2u(v3.x, v3.y);
    } else {
        u.x = h2u(v0.x, v0.y); u.y = h2u(v1.x, v1.y);
        u.z = h2u(v2.x, v2.y); u.w = h2u(v3.x, v3.y);
    }
    dst[gid] = u;
}

__global__ void __launch_bounds__(256) convert5_kernel(
    const float* __restrict__ x,  const float* __restrict__ wq,
    const float* __restrict__ wk, const float* __restrict__ wv,
    const float* __restrict__ wo)
{
    int slot = blockIdx.y;
    const float* src = (slot == 0) ? x : (slot == 1) ? wq :
                       (slot == 2) ? wk : (slot == 3) ? wv : wo;
    unsigned gid = blockIdx.x * 256 + threadIdx.x;
    permute_one(src, g_p + (size_t)slot * SLOT_H, gid, slot != 0);
}

/* ---------------- KV tile permute (64 j x 128 d staged in smem, fp16 out) ---- */
__device__ __forceinline__ void kv_permute_tile(
    const float* __restrict__ src, float* Ts, int tt, int bh, int isV, int tid)
{
    const int lane = tid & 31, g = lane >> 2, tg = lane & 3;
    __syncthreads();
    #pragma unroll
    for (int p = 0; p < 8; p++) {
        int idx = tid + p * 256;
        int r = idx >> 5, c4 = (idx & 31) << 2;
        *(float4*)&Ts[r * 132 + c4] = *(const float4*)(src + (size_t)r * EMB + c4);
    }
    __syncthreads();
    if (!isV) {
        uint4* dst = g_kp + (size_t)bh * 65536 + (size_t)tt * 1024;
        #pragma unroll
        for (int p = 0; p < 4; p++) {
            int idx = tid + p * 256;                 /* (NI*8+KS)*32+lane */
            int KS = (idx >> 5) & 7, NI = idx >> 8;
            int j = NI * 16 + g, d = KS * 16 + 2 * tg;
            uint4 u;
            u.x = h2u(Ts[j * 132 + d],           Ts[j * 132 + d + 1]);
            u.y = h2u(Ts[j * 132 + d + 8],       Ts[j * 132 + d + 9]);
            u.z = h2u(Ts[(j + 8) * 132 + d],     Ts[(j + 8) * 132 + d + 1]);
            u.w = h2u(Ts[(j + 8) * 132 + d + 8], Ts[(j + 8) * 132 + d + 9]);
            dst[idx] = u;
        }
    } else {
        uint4* dst = g_vp + (size_t)bh * 65536;
        #pragma unroll
        for (int p = 0; p < 4; p++) {
            int idx = tid + p * 256;                 /* NI*128 + KSj*32 + lane */
            int KSj = (idx >> 5) & 3, NI = idx >> 7;
            int j = KSj * 16 + 2 * tg, d = NI * 16 + g;
            uint4 u;
            u.x = h2u(Ts[j * 132 + d],           Ts[(j + 1) * 132 + d]);
            u.y = h2u(Ts[(j + 8) * 132 + d],     Ts[(j + 9) * 132 + d]);
            u.z = h2u(Ts[j * 132 + d + 8],       Ts[(j + 1) * 132 + d + 8]);
            u.w = h2u(Ts[(j + 8) * 132 + d + 8], Ts[(j + 9) * 132 + d + 8]);
            dst[(size_t)NI * 8192 + (tt * 4 + KSj) * 32 + (idx & 31)] = u;
        }
    }
}

/* permute NEW kv region (from g_k/g_v). 1024 blocks. */
__global__ void __launch_bounds__(256) permute_new_kernel()
{
    __shared__ float Ts[64 * 132];
    int job = blockIdx.x;
    int isV = job >= 512;
    int jj = job & 511;
    int bh = jj >> 3, tl = jj & 7;
    int b = bh >> 4, h = bh & 15;
    const float* src = (isV ? g_v : g_k) + ((size_t)(b * TGT) + tl * 64) * EMB + h * HD;
    kv_permute_tile(src, Ts, 56 + tl, bh, isV, threadIdx.x);
}

/* ---------------- dense GEMM: C[128,128] = A @ B^T, fp16 fragments ---------- */
#define GSTG 1024
#define GEMM_SMEM (3 * GSTG * 16)

__device__ __forceinline__ void gemm_main(
    const uint4* __restrict__ Ag, const uint4* __restrict__ Bg,
    float c[4][4][4], uint4* S, int tid)
{
    const int lane = tid & 31, wid = tid >> 5;
    const int wm = wid >> 2, wn = wid & 3;

    #pragma unroll
    for (int st = 0; st < 2; st++) {
        #pragma unroll
        for (int i = 0; i < 4; i++) {
            int ch = tid + i * 256;
            int half = ch >> 9, cc = ch & 511;
            int mi = cc >> 6, ksl = (cc >> 5) & 1, l = cc & 31;
            const uint4* src = (half ? Bg : Ag)
                + (size_t)mi * 4096 + (2 * st + ksl) * 32 + l;
            cp16(sm_u32(S + st * GSTG + half * 512 + cc), src);
        }
        CP_COMMIT();
    }

    for (int kt = 0; kt < 64; kt++) {
        if (kt < 63) CP_WAIT(1); else CP_WAIT(0);
        __syncthreads();

        if (kt + 2 < 64) {
            int st = (kt + 2) % 3;
            #pragma unroll
            for (int i = 0; i < 4; i++) {
                int ch = tid + i * 256;
                int half = ch >> 9, cc = ch & 511;
                int mi = cc >> 6, ksl = (cc >> 5) & 1, l = cc & 31;
                const uint4* src = (half ? Bg : Ag)
                    + (size_t)mi * 4096 + (2 * (kt + 2) + ksl) * 32 + l;
                cp16(sm_u32(S + st * GSTG + half * 512 + cc), src);
            }
            CP_COMMIT();
        }

        const uint4* Af = S + (kt % 3) * GSTG;
        const uint4* Bf = Af + 512;
        #pragma unroll
        for (int ks = 0; ks < 2; ks++) {
            uint4 a[4], bu[2];
            #pragma unroll
            for (int mt = 0; mt < 4; mt++)
                a[mt] = Af[((wm * 4 + mt) * 2 + ks) * 32 + lane];
            #pragma unroll
            for (int p = 0; p < 2; p++)
                bu[p] = Bf[((wn * 2 + p) * 2 + ks) * 32 + lane];
            #pragma unroll
            for (int mt = 0; mt < 4; mt++) {
                mma8(c[mt][0], a[mt], bu[0].x, bu[0].y);
                mma8(c[mt][1], a[mt], bu[0].z, bu[0].w);
                mma8(c[mt][2], a[mt], bu[1].x, bu[1].y);
                mma8(c[mt][3], a[mt], bu[1].z, bu[1].w);
            }
        }
    }
}

/* Fused QKV + interleaved old-KV permute plane. grid (96,16). */
__global__ void __launch_bounds__(256, 2) qkv_kernel(
    const float* __restrict__ kc_in, const float* __restrict__ vc_in,
    const float* __restrict__ bq, const float* __restrict__ bk,
    const float* __restrict__ bv,
    float* __restrict__ okc, float* __restrict__ ovc, int write_cache)
{
    extern __shared__ uint4 S[];
    const int tid = threadIdx.x;

    if (blockIdx.x >= 48) {
        float* Ts = (float*)S;
        int pbid = (blockIdx.x - 48) + 48 * blockIdx.y;
        for (int job = pbid; job < 7168; job += 768) {
            int isV = job >= 3584;
            int jj = isV ? job - 3584 : job;
            int bh = jj / 56, tt = jj % 56;
            int b = bh >> 4, h = bh & 15;
            const float* src = (isV ? vc_in : kc_in)
                + ((size_t)(b * KVLEN) + tt * 64) * EMB + h * HD;
            kv_permute_tile(src, Ts, tt, bh, isV, tid);
        }
        return;
    }

    const int lane = tid & 31, wid = tid >> 5;
    const int g = lane >> 2, tg = lane & 3;
    const int wm = wid >> 2, wn = wid & 3;
    const int nb = blockIdx.x, mb = blockIdx.y;
    const int sel = nb >> 4, nblk = nb & 15;
    const float* bias = (sel == 0) ? bq : (sel == 1) ? bk : bv;

    const uint4* Ag = g_p + (size_t)mb * 32768;
    const uint4* Bg = g_p + (size_t)(1 + sel) * SLOT_H + (size_t)nblk * 32768;

    float c[4][4][4] = {};
    gemm_main(Ag, Bg, c, S, tid);

    #pragma unroll
    for (int mt = 0; mt < 4; mt++) {
        #pragma unroll
        for (int nt = 0; nt < 4; nt++) {
            int col = nblk * 128 + wn * 32 + nt * 8 + 2 * tg;
            #pragma unroll
            for (int half = 0; half < 2; half++) {
                int m = mb * 128 + wm * 64 + mt * 16 + g + half * 8;
                float v0 = c[mt][nt][half * 2 + 0] + bias[col];
                float v1 = c[mt][nt][half * 2 + 1] + bias[col + 1];
                if (sel == 0) {
                    g_q[(size_t)m * EMB + col]     = v0 * QSCALE;
                    g_q[(size_t)m * EMB + col + 1] = v1 * QSCALE;
                } else {
                    float* dst = (sel == 1) ? g_k : g_v;
                    dst[(size_t)m * EMB + col]     = v0;
                    dst[(size_t)m * EMB + col + 1] = v1;
                    if (write_cache) {
                        int bidx = m >> 9, t = m & 511;
                        float* cd = (sel == 1) ? okc : ovc;
                        size_t o = ((size_t)bidx * KVLEN + KVOLD + t) * EMB + col;
                        cd[o] = v0; cd[o + 1] = v1;
                    }
                }
            }
        }
    }
}

/* Output projection: grid (16,16). A = fp16-permuted attn (slot 5). */
__global__ void __launch_bounds__(256, 2) proj_kernel(
    const float* __restrict__ bo, float* __restrict__ out)
{
    extern __shared__ uint4 S[];
    const int tid = threadIdx.x;
    const int lane = tid & 31, wid = tid >> 5;
    const int g = lane >> 2, tg = lane & 3;
    const int wm = wid >> 2, wn = wid & 3;
    const int nblk = blockIdx.x, mb = blockIdx.y;

    const uint4* Ag = g_p + 5 * (size_t)SLOT_H + (size_t)mb * 32768;
    const uint4* Bg = g_p + 4 * (size_t)SLOT_H + (size_t)nblk * 32768;

    float c[4][4][4] = {};
    gemm_main(Ag, Bg, c, S, tid);

    #pragma unroll
    for (int mt = 0; mt < 4; mt++)
        #pragma unroll
        for (int nt = 0; nt < 4; nt++) {
            int col = nblk * 128 + wn * 32 + nt * 8 + 2 * tg;
            #pragma unroll
            for (int half = 0; half < 2; half++) {
                int m = mb * 128 + wm * 64 + mt * 16 + g + half * 8;
                out[(size_t)m * EMB + col]     = c[mt][nt][half * 2 + 0] + bo[col];
                out[(size_t)m * EMB + col + 1] = c[mt][nt][half * 2 + 1] + bo[col + 1];
            }
        }
}

/* ---------------- flash attention: warp-autonomous rows, fp16 ----------------
   256 thr, 8 warps; warp w owns rows [w*16, w*16+16) x ALL 64 KV cols.
   Q A-frags in registers (warp-private). P repacked in-lane from S c-frags
   to A-frags (never touches smem). No cross-warp softmax: quad shuffles only.
   One __syncthreads per tile (K/V publish). Deferred-PV retained.
   smem (uint4): K 2x1024 | V 2x1024 = 4096 u4 = 64 KB; epilogue St overlays
   (128x132 f32 = 67584 B) -> ATT_SMEM = 67584.                              */
#define OVV 2048
#define ATT_SMEM (128 * 132 * 4)
#define NT (KVLEN / 64)

__global__ void __launch_bounds__(256, 1) attn_kernel(
    const float* __restrict__ kc_in, const float* __restrict__ vc_in,
    const float* __restrict__ mask,
    float* __restrict__ okc, float* __restrict__ ovc, int write_cache)
{
    if (blockIdx.z == BSZ) {
        if (write_cache) {
            const int cb = blockIdx.x + gridDim.x * blockIdx.y;   /* 0..63 */
            const int N4 = KVOLD * EMB / 4;
            #pragma unroll 1
            for (int b = 0; b < BSZ; b++) {
                const float4* sk = (const float4*)(kc_in + (size_t)b * KVLEN * EMB);
                const float4* sv = (const float4*)(vc_in + (size_t)b * KVLEN * EMB);
                float4* dk = (float4*)(okc + (size_t)b * KVLEN * EMB);
                float4* dv = (float4*)(ovc + (size_t)b * KVLEN * EMB);
                for (int i = cb * 256 + (int)threadIdx.x; i < N4; i += 64 * 256) {
                    dk[i] = sk[i];
                    dv[i] = sv[i];
                }
            }
        }
        return;
    }

    extern __shared__ uint4 smq[];

    const int tid  = threadIdx.x;
    const int lane = tid & 31, wid = tid >> 5;
    const int g = lane >> 2, tg = lane & 3;
    const int qt = blockIdx.x, h = blockIdx.y, b = blockIdx.z;

    const uint4* gK = g_kp + (size_t)(b * 16 + h) * 65536;
    const uint4* gV = g_vp + (size_t)(b * 16 + h) * 65536;
    const int R0 = wid * 16 + g;
    const int R1 = R0 + 8;
    const float* mrow0 = mask + (size_t)(qt * 128 + R0) * KVLEN;
    const float* mrow1 = mask + (size_t)(qt * 128 + R1) * KVLEN;

    /* prologue: K(0) */
    #pragma unroll
    for (int p = 0; p < 4; p++) {
        int idx = tid + p * 256;
        cp16(sm_u32(smq + idx), gK + idx);
    }
    CP_COMMIT();

    /* Q A-frags in registers: warp owns MI = wid, KS 0..7 */
    uint4 qr[8];
    {
        const float* qb = g_q + (size_t)(b * TGT + qt * 128 + wid * 16 + g) * EMB + h * HD;
        #pragma unroll
        for (int ks = 0; ks < 8; ks++) {
            const float* p = qb + ks * 16 + 2 * tg;
            float2 v0 = *(const float2*)(p);
            float2 v1 = *(const float2*)(p + 8 * EMB);
            float2 v2 = *(const float2*)(p + 8);
            float2 v3 = *(const float2*)(p + 8 * EMB + 8);
            qr[ks].x = h2u(v0.x, v0.y); qr[ks].y = h2u(v1.x, v1.y);
            qr[ks].z = h2u(v2.x, v2.y); qr[ks].w = h2u(v3.x, v3.y);
        }
    }

    float m0 = -1e30f, m1 = -1e30f, l0 = 0.f, l1 = 0.f;
    float o[16][4] = {};
    uint4 pa[4];   /* deferred P A-frags (previous tile) */

    #pragma unroll 1
    for (int t = 0; t < NT; t++) {
        /* mask prefetch */
        float2 mA[8], mB[8];
        #pragma unroll
        for (int nt = 0; nt < 8; nt++) {
            int col = t * 64 + nt * 8 + 2 * tg;
            mA[nt] = *(const float2*)(mrow0 + col);
            mB[nt] = *(const float2*)(mrow1 + col);
        }

        CP_WAIT(0);          /* group(t-1): K(t) + V(t-1) ready */
        __syncthreads();     /* single CTA barrier per tile */

        /* issue group(t): K(t+1), V(t) */
        if (t + 1 < NT) {
            #pragma unroll
            for (int p = 0; p < 4; p++) {
                int idx = tid + p * 256;
                cp16(sm_u32(smq + ((t + 1) & 1) * 1024 + idx),
                     gK + (size_t)(t + 1) * 1024 + idx);
            }
        }
        #pragma unroll
        for (int p = 0; p < 4; p++) {
            int idx = tid + p * 256;
            cp16(sm_u32(smq + OVV + (t & 1) * 1024 + idx),
                 gV + (size_t)(idx >> 7) * 8192 + t * 128 + (idx & 127));
        }
        CP_COMMIT();

        const uint4* Kc = smq + (t & 1) * 1024;

        /* S(t) = Q K^T : warp m16 x n64, 8 k16-slices */
        float s[8][4] = {};
        #pragma unroll
        for (int ks = 0; ks < 8; ks++) {
            uint4 a = qr[ks];
            #pragma unroll
            for (int ni = 0; ni < 4; ni++) {
                uint4 KB = Kc[(ni * 8 + ks) * 32 + lane];
                mma8(s[2 * ni],     a, KB.x, KB.y);
                mma8(s[2 * ni + 1], a, KB.z, KB.w);
            }
        }

        /* PV(t-1): queued behind S(t); drains under the softmax below */
        if (t > 0) {
            const uint4* Vc = smq + OVV + ((t & 1) ^ 1) * 1024;
            #pragma unroll
            for (int ksj = 0; ksj < 4; ksj++) {
                uint4 a = pa[ksj];
                #pragma unroll
                for (int ni = 0; ni < 8; ni++) {
                    uint4 v = Vc[(ni * 4 + ksj) * 32 + lane];
                    mma8(o[2 * ni],     a, v.x, v.y);
                    mma8(o[2 * ni + 1], a, v.z, v.w);
                }
            }
        }

        /* softmax(t): fully warp-local (quad shuffles) */
        float mx0 = -1e30f, mx1 = -1e30f;
        #pragma unroll
        for (int nt = 0; nt < 8; nt++) {
            s[nt][0] += mA[nt].x; s[nt][1] += mA[nt].y;
            s[nt][2] += mB[nt].x; s[nt][3] += mB[nt].y;
            mx0 = fmaxf(mx0, fmaxf(s[nt][0], s[nt][1]));
            mx1 = fmaxf(mx1, fmaxf(s[nt][2], s[nt][3]));
        }
        mx0 = fmaxf(mx0, __shfl_xor_sync(0xffffffffu, mx0, 1));
        mx0 = fmaxf(mx0, __shfl_xor_sync(0xffffffffu, mx0, 2));
        mx1 = fmaxf(mx1, __shfl_xor_sync(0xffffffffu, mx1, 1));
        mx1 = fmaxf(mx1, __shfl_xor_sync(0xffffffffu, mx1, 2));
        float mn0 = fmaxf(m0, mx0);
        float mn1 = fmaxf(m1, mx1);

        float s0s = 0.f, s1s = 0.f;
        #pragma unroll
        for (int nt = 0; nt < 8; nt++) {
            s[nt][0] = __expf(s[nt][0] - mn0);
            s[nt][1] = __expf(s[nt][1] - mn0);
            s[nt][2] = __expf(s[nt][2] - mn1);
            s[nt][3] = __expf(s[nt][3] - mn1);
            s0s += s[nt][0] + s[nt][1];
            s1s += s[nt][2] + s[nt][3];
        }
        s0s += __shfl_xor_sync(0xffffffffu, s0s, 1);
        s0s += __shfl_xor_sync(0xffffffffu, s0s, 2);
        s1s += __shfl_xor_sync(0xffffffffu, s1s, 1);
        s1s += __shfl_xor_sync(0xffffffffu, s1s, 2);

        float sc0 = __expf(m0 - mn0), sc1 = __expf(m1 - mn1);
        l0 = l0 * sc0 + s0s;
        l1 = l1 * sc1 + s1s;
        m0 = mn0; m1 = mn1;
        #pragma unroll
        for (int nt = 0; nt < 16; nt++) {
            o[nt][0] *= sc0; o[nt][1] *= sc0;
            o[nt][2] *= sc1; o[nt][3] *= sc1;
        }

        /* pack P c-frags -> A-frags IN-LANE (no smem, no shuffle) */
        #pragma unroll
        for (int KS = 0; KS < 4; KS++) {
            pa[KS].x = h2u(s[2 * KS][0],     s[2 * KS][1]);
            pa[KS].y = h2u(s[2 * KS][2],     s[2 * KS][3]);
            pa[KS].z = h2u(s[2 * KS + 1][0], s[2 * KS + 1][1]);
            pa[KS].w = h2u(s[2 * KS + 1][2], s[2 * KS + 1][3]);
        }
    }

    /* drain: PV(NT-1) */
    CP_WAIT(0);
    __syncthreads();
    {
        const uint4* Vc = smq + OVV + ((NT - 1) & 1) * 1024;
        #pragma unroll
        for (int ksj = 0; ksj < 4; ksj++) {
            uint4 a = pa[ksj];
            #pragma unroll
            for (int ni = 0; ni < 8; ni++) {
                uint4 v = Vc[(ni * 4 + ksj) * 32 + lane];
                mma8(o[2 * ni],     a, v.x, v.y);
                mma8(o[2 * ni + 1], a, v.z, v.w);
            }
        }
    }

    /* fused epilogue: normalize, stage f32, write fp16 A-frags to slot 5 */
    __syncthreads();
    float* St = (float*)smq;   /* 128 x 132 floats */
    {
        float inv0 = 1.f / l0, inv1 = 1.f / l1;
        #pragma unroll
        for (int nt = 0; nt < 16; nt++) {
            int c = nt * 8 + 2 * tg;
            St[R0 * 132 + c]     = o[nt][0] * inv0;
            St[R0 * 132 + c + 1] = o[nt][1] * inv0;
            St[R1 * 132 + c]     = o[nt][2] * inv1;
            St[R1 * 132 + c + 1] = o[nt][3] * inv1;
        }
    }
    __syncthreads();
    {
        uint4* gp5 = g_p + 5 * (size_t)SLOT_H;
        const int gMIb = b * 32 + qt * 8;
        #pragma unroll
        for (int MI = 0; MI < 8; MI++) {
            int r = MI * 16 + g, c = wid * 16 + 2 * tg;
            uint4 u;
            u.x = h2u(St[r * 132 + c],           St[r * 132 + c + 1]);
            u.y = h2u(St[(r + 8) * 132 + c],     St[(r + 8) * 132 + c + 1]);
            u.z = h2u(St[r * 132 + c + 8],       St[r * 132 + c + 9]);
            u.w = h2u(St[(r + 8) * 132 + c + 8], St[(r + 8) * 132 + c + 9]);
            gp5[((size_t)(gMIb + MI) * 128 + (h * 8 + wid)) * 32 + lane] = u;
        }
    }
}

/* ------------------------------------------------------------------ */
extern "C" void kernel_launch(void* const* d_in, const int* in_sizes, int n_in,
                              void* d_out, int out_size)
{
    const float* x       = (const float*)d_in[0];
    const float* k_cache = (const float*)d_in[1];
    const float* v_cache = (const float*)d_in[2];
    const float* mask    = (const float*)d_in[3];
    const float* wq = (const float*)d_in[4];
    const float* bq = (const float*)d_in[5];
    const float* wk = (const float*)d_in[6];
    const float* bk = (const float*)d_in[7];
    const float* wv = (const float*)d_in[8];
    const float* bv = (const float*)d_in[9];
    const float* wo = (const float*)d_in[10];
    const float* bo = (const float*)d_in[11];

    float* out = (float*)d_out;
    long long need = (long long)MROWS * EMB + 2LL * BSZ * KVLEN * EMB;
    int write_cache = ((long long)out_size >= need) ? 1 : 0;
    float* okc = out + (size_t)MROWS * EMB;
    float* ovc = okc + (size_t)BSZ * KVLEN * EMB;

    cudaFuncSetAttribute(attn_kernel,
                         cudaFuncAttributeMaxDynamicSharedMemorySize, ATT_SMEM);
    cudaFuncSetAttribute(qkv_kernel,
                         cudaFuncAttributeMaxDynamicSharedMemorySize, GEMM_SMEM);
    cudaFuncSetAttribute(proj_kernel,
                         cudaFuncAttributeMaxDynamicSharedMemorySize, GEMM_SMEM);

    convert5_kernel<<<dim3(2048, 5), 256>>>(x, wq, wk, wv, wo);
    qkv_kernel<<<dim3(96, 16), 256, GEMM_SMEM>>>(k_cache, v_cache,
                                                 bq, bk, bv, okc, ovc, write_cache);
    permute_new_kernel<<<1024, 256>>>();
    attn_kernel<<<dim3(4, 16, BSZ + 1), 256, ATT_SMEM>>>(k_cache, v_cache, mask,
                                                         okc, ovc, write_cache);
    proj_kernel<<<dim3(16, 16), 256, GEMM_SMEM>>>(bo, out);
}

// round 15
// speedup vs baseline: 1.7382x; 1.0220x over previous
#include <cuda_runtime.h>
#include <cuda_fp16.h>

#define BSZ   4
#define TGT   512
#define KVLEN 4096
#define KVOLD (KVLEN - TGT)   /* 3584 */
#define EMB   2048
#define NH    16
#define HD    128
#define MROWS (BSZ * TGT)     /* 2048 */
#define SLOT_H 524288         /* uint4 per fp16-permuted 2048x2048 matrix */
#define QSCALE 0.08838834764831845f  /* 128^-0.5 */
#define LOG2E  1.4426950408889634f
#define QS2    (QSCALE * LOG2E)      /* folded: softmax runs in exp2 domain */

/* scratch (static device arrays: allocation-free per harness rules) */
__device__ float g_q[MROWS * EMB];
__device__ float g_k[MROWS * EMB];
__device__ float g_v[MROWS * EMB];
/* permuted fp16 operands: 0=x(A) 1=wq(B) 2=wk(B) 3=wv(B) 4=wo(B) 5=attn(A) */
__device__ uint4 g_p[6 * SLOT_H];                /* 48 MB */
/* permuted fp16 KV cache, fragment layout, per (b,h): 65536 uint4 */
__device__ uint4 g_kp[64 * 65536];               /* 64 MB */
__device__ uint4 g_vp[64 * 65536];               /* 64 MB */

/* ---------------- helpers ---------------- */
__device__ __forceinline__ unsigned h2u(float lo, float hi) {
    unsigned u;
    asm("cvt.rn.f16x2.f32 %0, %1, %2;" : "=r"(u) : "f"(hi), "f"(lo));
    return u;
}
__device__ __forceinline__ void mma8(float c[4], const uint4& a, unsigned b0, unsigned b1) {
    asm("mma.sync.aligned.m16n8k16.row.col.f32.f16.f16.f32 "
        "{%0,%1,%2,%3},{%4,%5,%6,%7},{%8,%9},{%0,%1,%2,%3};"
        : "+f"(c[0]), "+f"(c[1]), "+f"(c[2]), "+f"(c[3])
        : "r"(a.x), "r"(a.y), "r"(a.z), "r"(a.w), "r"(b0), "r"(b1));
}
__device__ __forceinline__ unsigned sm_u32(const void* p) {
    return (unsigned)__cvta_generic_to_shared(p);
}
__device__ __forceinline__ void cp16(unsigned dst, const void* src) {
    asm volatile("cp.async.cg.shared.global [%0], [%1], 16;" :: "r"(dst), "l"(src));
}
#define CP_COMMIT() asm volatile("cp.async.commit_group;")
#define CP_WAIT(n)  asm volatile("cp.async.wait_group %0;" :: "n"(n))

/* ---------------- dense-operand permute (fp16 A/B fragment layouts) ---------- */
__device__ __forceinline__ void permute_one(const float* __restrict__ src,
                                            uint4* __restrict__ dst,
                                            unsigned gid, int btype)
{
    unsigned lane = gid & 31, KS = (gid >> 5) & 127, MI = gid >> 12;
    unsigned g = lane >> 2, tg = lane & 3;
    const float* p = src + (size_t)(MI * 16 + g) * EMB + KS * 16 + 2 * tg;
    float2 v0 = *(const float2*)(p);
    float2 v1 = *(const float2*)(p + 8 * EMB);
    float2 v2 = *(const float2*)(p + 8);
    float2 v3 = *(const float2*)(p + 8 * EMB + 8);
    uint4 u;
    if (btype) {
        u.x = h2u(v0.x, v0.y); u.y = h2u(v2.x, v2.y);
        u.z = h2u(v1.x, v1.y); u.w = h2u(v3.x, v3.y);
    } else {
        u.x = h2u(v0.x, v0.y); u.y = h2u(v1.x, v1.y);
        u.z = h2u(v2.x, v2.y); u.w = h2u(v3.x, v3.y);
    }
    dst[gid] = u;
}

__global__ void __launch_bounds__(256) convert5_kernel(
    const float* __restrict__ x,  const float* __restrict__ wq,
    const float* __restrict__ wk, const float* __restrict__ wv,
    const float* __restrict__ wo)
{
    int slot = blockIdx.y;
    const float* src = (slot == 0) ? x : (slot == 1) ? wq :
                       (slot == 2) ? wk : (slot == 3) ? wv : wo;
    unsigned gid = blockIdx.x * 256 + threadIdx.x;
    permute_one(src, g_p + (size_t)slot * SLOT_H, gid, slot != 0);
}

/* ---------------- KV tile permute (64 j x 128 d staged in smem, fp16 out) ---- */
__device__ __forceinline__ void kv_permute_tile(
    const float* __restrict__ src, float* Ts, int tt, int bh, int isV, int tid)
{
    const int lane = tid & 31, g = lane >> 2, tg = lane & 3;
    __syncthreads();
    #pragma unroll
    for (int p = 0; p < 8; p++) {
        int idx = tid + p * 256;
        int r = idx >> 5, c4 = (idx & 31) << 2;
        *(float4*)&Ts[r * 132 + c4] = *(const float4*)(src + (size_t)r * EMB + c4);
    }
    __syncthreads();
    if (!isV) {
        uint4* dst = g_kp + (size_t)bh * 65536 + (size_t)tt * 1024;
        #pragma unroll
        for (int p = 0; p < 4; p++) {
            int idx = tid + p * 256;                 /* (NI*8+KS)*32+lane */
            int KS = (idx >> 5) & 7, NI = idx >> 8;
            int j = NI * 16 + g, d = KS * 16 + 2 * tg;
            uint4 u;
            u.x = h2u(Ts[j * 132 + d],           Ts[j * 132 + d + 1]);
            u.y = h2u(Ts[j * 132 + d + 8],       Ts[j * 132 + d + 9]);
            u.z = h2u(Ts[(j + 8) * 132 + d],     Ts[(j + 8) * 132 + d + 1]);
            u.w = h2u(Ts[(j + 8) * 132 + d + 8], Ts[(j + 8) * 132 + d + 9]);
            dst[idx] = u;
        }
    } else {
        uint4* dst = g_vp + (size_t)bh * 65536;
        #pragma unroll
        for (int p = 0; p < 4; p++) {
            int idx = tid + p * 256;                 /* NI*128 + KSj*32 + lane */
            int KSj = (idx >> 5) & 3, NI = idx >> 7;
            int j = KSj * 16 + 2 * tg, d = NI * 16 + g;
            uint4 u;
            u.x = h2u(Ts[j * 132 + d],           Ts[(j + 1) * 132 + d]);
            u.y = h2u(Ts[(j + 8) * 132 + d],     Ts[(j + 9) * 132 + d]);
            u.z = h2u(Ts[j * 132 + d + 8],       Ts[(j + 1) * 132 + d + 8]);
            u.w = h2u(Ts[(j + 8) * 132 + d + 8], Ts[(j + 9) * 132 + d + 8]);
            dst[(size_t)NI * 8192 + (tt * 4 + KSj) * 32 + (idx & 31)] = u;
        }
    }
}

/* permute NEW kv region (from g_k/g_v). 1024 blocks. */
__global__ void __launch_bounds__(256) permute_new_kernel()
{
    __shared__ float Ts[64 * 132];
    int job = blockIdx.x;
    int isV = job >= 512;
    int jj = job & 511;
    int bh = jj >> 3, tl = jj & 7;
    int b = bh >> 4, h = bh & 15;
    const float* src = (isV ? g_v : g_k) + ((size_t)(b * TGT) + tl * 64) * EMB + h * HD;
    kv_permute_tile(src, Ts, 56 + tl, bh, isV, threadIdx.x);
}

/* ---------------- dense GEMM: C[128,128] = A @ B^T, fp16 fragments ---------- */
#define GSTG 1024
#define GEMM_SMEM (3 * GSTG * 16)

__device__ __forceinline__ void gemm_main(
    const uint4* __restrict__ Ag, const uint4* __restrict__ Bg,
    float c[4][4][4], uint4* S, int tid)
{
    const int lane = tid & 31, wid = tid >> 5;
    const int wm = wid >> 2, wn = wid & 3;

    #pragma unroll
    for (int st = 0; st < 2; st++) {
        #pragma unroll
        for (int i = 0; i < 4; i++) {
            int ch = tid + i * 256;
            int half = ch >> 9, cc = ch & 511;
            int mi = cc >> 6, ksl = (cc >> 5) & 1, l = cc & 31;
            const uint4* src = (half ? Bg : Ag)
                + (size_t)mi * 4096 + (2 * st + ksl) * 32 + l;
            cp16(sm_u32(S + st * GSTG + half * 512 + cc), src);
        }
        CP_COMMIT();
    }

    for (int kt = 0; kt < 64; kt++) {
        if (kt < 63) CP_WAIT(1); else CP_WAIT(0);
        __syncthreads();

        if (kt + 2 < 64) {
            int st = (kt + 2) % 3;
            #pragma unroll
            for (int i = 0; i < 4; i++) {
                int ch = tid + i * 256;
                int half = ch >> 9, cc = ch & 511;
                int mi = cc >> 6, ksl = (cc >> 5) & 1, l = cc & 31;
                const uint4* src = (half ? Bg : Ag)
                    + (size_t)mi * 4096 + (2 * (kt + 2) + ksl) * 32 + l;
                cp16(sm_u32(S + st * GSTG + half * 512 + cc), src);
            }
            CP_COMMIT();
        }

        const uint4* Af = S + (kt % 3) * GSTG;
        const uint4* Bf = Af + 512;
        #pragma unroll
        for (int ks = 0; ks < 2; ks++) {
            uint4 a[4], bu[2];
            #pragma unroll
            for (int mt = 0; mt < 4; mt++)
                a[mt] = Af[((wm * 4 + mt) * 2 + ks) * 32 + lane];
            #pragma unroll
            for (int p = 0; p < 2; p++)
                bu[p] = Bf[((wn * 2 + p) * 2 + ks) * 32 + lane];
            #pragma unroll
            for (int mt = 0; mt < 4; mt++) {
                mma8(c[mt][0], a[mt], bu[0].x, bu[0].y);
                mma8(c[mt][1], a[mt], bu[0].z, bu[0].w);
                mma8(c[mt][2], a[mt], bu[1].x, bu[1].y);
                mma8(c[mt][3], a[mt], bu[1].z, bu[1].w);
            }
        }
    }
}

/* Fused QKV + interleaved old-KV permute plane. grid (96,16). */
__global__ void __launch_bounds__(256, 2) qkv_kernel(
    const float* __restrict__ kc_in, const float* __restrict__ vc_in,
    const float* __restrict__ bq, const float* __restrict__ bk,
    const float* __restrict__ bv,
    float* __restrict__ okc, float* __restrict__ ovc, int write_cache)
{
    extern __shared__ uint4 S[];
    const int tid = threadIdx.x;

    if (blockIdx.x >= 48) {
        float* Ts = (float*)S;
        int pbid = (blockIdx.x - 48) + 48 * blockIdx.y;
        for (int job = pbid; job < 7168; job += 768) {
            int isV = job >= 3584;
            int jj = isV ? job - 3584 : job;
            int bh = jj / 56, tt = jj % 56;
            int b = bh >> 4, h = bh & 15;
            const float* src = (isV ? vc_in : kc_in)
                + ((size_t)(b * KVLEN) + tt * 64) * EMB + h * HD;
            kv_permute_tile(src, Ts, tt, bh, isV, tid);
        }
        return;
    }

    const int lane = tid & 31, wid = tid >> 5;
    const int g = lane >> 2, tg = lane & 3;
    const int wm = wid >> 2, wn = wid & 3;
    const int nb = blockIdx.x, mb = blockIdx.y;
    const int sel = nb >> 4, nblk = nb & 15;
    const float* bias = (sel == 0) ? bq : (sel == 1) ? bk : bv;

    const uint4* Ag = g_p + (size_t)mb * 32768;
    const uint4* Bg = g_p + (size_t)(1 + sel) * SLOT_H + (size_t)nblk * 32768;

    float c[4][4][4] = {};
    gemm_main(Ag, Bg, c, S, tid);

    #pragma unroll
    for (int mt = 0; mt < 4; mt++) {
        #pragma unroll
        for (int nt = 0; nt < 4; nt++) {
            int col = nblk * 128 + wn * 32 + nt * 8 + 2 * tg;
            #pragma unroll
            for (int half = 0; half < 2; half++) {
                int m = mb * 128 + wm * 64 + mt * 16 + g + half * 8;
                float v0 = c[mt][nt][half * 2 + 0] + bias[col];
                float v1 = c[mt][nt][half * 2 + 1] + bias[col + 1];
                if (sel == 0) {
                    /* exp2-domain fold: scale by 1/sqrt(d) * log2(e) */
                    g_q[(size_t)m * EMB + col]     = v0 * QS2;
                    g_q[(size_t)m * EMB + col + 1] = v1 * QS2;
                } else {
                    float* dst = (sel == 1) ? g_k : g_v;
                    dst[(size_t)m * EMB + col]     = v0;
                    dst[(size_t)m * EMB + col + 1] = v1;
                    if (write_cache) {
                        int bidx = m >> 9, t = m & 511;
                        float* cd = (sel == 1) ? okc : ovc;
                        size_t o = ((size_t)bidx * KVLEN + KVOLD + t) * EMB + col;
                        cd[o] = v0; cd[o + 1] = v1;
                    }
                }
            }
        }
    }
}

/* Output projection: grid (16,16). A = fp16-permuted attn (slot 5). */
__global__ void __launch_bounds__(256, 2) proj_kernel(
    const float* __restrict__ bo, float* __restrict__ out)
{
    extern __shared__ uint4 S[];
    const int tid = threadIdx.x;
    const int lane = tid & 31, wid = tid >> 5;
    const int g = lane >> 2, tg = lane & 3;
    const int wm = wid >> 2, wn = wid & 3;
    const int nblk = blockIdx.x, mb = blockIdx.y;

    const uint4* Ag = g_p + 5 * (size_t)SLOT_H + (size_t)mb * 32768;
    const uint4* Bg = g_p + 4 * (size_t)SLOT_H + (size_t)nblk * 32768;

    float c[4][4][4] = {};
    gemm_main(Ag, Bg, c, S, tid);

    #pragma unroll
    for (int mt = 0; mt < 4; mt++)
        #pragma unroll
        for (int nt = 0; nt < 4; nt++) {
            int col = nblk * 128 + wn * 32 + nt * 8 + 2 * tg;
            #pragma unroll
            for (int half = 0; half < 2; half++) {
                int m = mb * 128 + wm * 64 + mt * 16 + g + half * 8;
                out[(size_t)m * EMB + col]     = c[mt][nt][half * 2 + 0] + bo[col];
                out[(size_t)m * EMB + col + 1] = c[mt][nt][half * 2 + 1] + bo[col + 1];
            }
        }
}

/* ---------------- flash attention: 2 small CTAs/SM, exp2 softmax ------------
   128 thr, 4 warps; warp w owns rows [w*16, w*16+16) x ALL 64 KV cols.
   Q tile 64 -> 512 work CTAs; 2 CTAs co-resident per SM (regs ~232 -> 59K,
   smem 64KB each) give two independent instruction streams per SMSP: one
   CTA's softmax chain hides under the other's MMAs, and the wave tail evens
   out. Softmax in exp2 domain (log2e folded into Q and mask-add).
   smem (uint4): K 2x1024 | V 2x1024 = 4096 u4 = 64 KB.                      */
#define OVV 2048
#define ATT_SMEM (4096 * 16)
#define NT (KVLEN / 64)

__global__ void __launch_bounds__(128, 2) attn_kernel(
    const float* __restrict__ kc_in, const float* __restrict__ vc_in,
    const float* __restrict__ mask,
    float* __restrict__ okc, float* __restrict__ ovc, int write_cache)
{
    if (blockIdx.z == BSZ) {
        if (write_cache) {
            const int cb = blockIdx.x + gridDim.x * blockIdx.y;   /* 0..127 */
            const int N4 = KVOLD * EMB / 4;
            #pragma unroll 1
            for (int b = 0; b < BSZ; b++) {
                const float4* sk = (const float4*)(kc_in + (size_t)b * KVLEN * EMB);
                const float4* sv = (const float4*)(vc_in + (size_t)b * KVLEN * EMB);
                float4* dk = (float4*)(okc + (size_t)b * KVLEN * EMB);
                float4* dv = (float4*)(ovc + (size_t)b * KVLEN * EMB);
                for (int i = cb * 128 + (int)threadIdx.x; i < N4; i += 128 * 128) {
                    dk[i] = sk[i];
                    dv[i] = sv[i];
                }
            }
        }
        return;
    }

    extern __shared__ uint4 smq[];

    const int tid  = threadIdx.x;
    const int lane = tid & 31, wid = tid >> 5;          /* wid 0..3 */
    const int g = lane >> 2, tg = lane & 3;
    const int qt = blockIdx.x, h = blockIdx.y, b = blockIdx.z;

    const uint4* gK = g_kp + (size_t)(b * 16 + h) * 65536;
    const uint4* gV = g_vp + (size_t)(b * 16 + h) * 65536;
    const int R0 = wid * 16 + g;
    const int R1 = R0 + 8;
    const float* mrow0 = mask + (size_t)(qt * 64 + R0) * KVLEN;
    const float* mrow1 = mask + (size_t)(qt * 64 + R1) * KVLEN;

    /* prologue: K(0) */
    #pragma unroll
    for (int p = 0; p < 8; p++) {
        int idx = tid + p * 128;
        cp16(sm_u32(smq + idx), gK + idx);
    }
    CP_COMMIT();

    /* Q A-frags in registers (already scaled by QSCALE*log2e) */
    uint4 qr[8];
    {
        const float* qb = g_q + (size_t)(b * TGT + qt * 64 + wid * 16 + g) * EMB + h * HD;
        #pragma unroll
        for (int ks = 0; ks < 8; ks++) {
            const float* p = qb + ks * 16 + 2 * tg;
            float2 v0 = *(const float2*)(p);
            float2 v1 = *(const float2*)(p + 8 * EMB);
            float2 v2 = *(const float2*)(p + 8);
            float2 v3 = *(const float2*)(p + 8 * EMB + 8);
            qr[ks].x = h2u(v0.x, v0.y); qr[ks].y = h2u(v1.x, v1.y);
            qr[ks].z = h2u(v2.x, v2.y); qr[ks].w = h2u(v3.x, v3.y);
        }
    }

    float m0 = -1e30f, m1 = -1e30f, l0 = 0.f, l1 = 0.f;
    float o[16][4] = {};
    uint4 pa[4];   /* deferred P A-frags (previous tile) */

    #pragma unroll 1
    for (int t = 0; t < NT; t++) {
        /* mask prefetch */
        float2 mA[8], mB[8];
        #pragma unroll
        for (int nt = 0; nt < 8; nt++) {
            int col = t * 64 + nt * 8 + 2 * tg;
            mA[nt] = *(const float2*)(mrow0 + col);
            mB[nt] = *(const float2*)(mrow1 + col);
        }

        CP_WAIT(0);          /* group(t-1): K(t) + V(t-1) ready */
        __syncthreads();

        /* issue group(t): K(t+1), V(t) */
        if (t + 1 < NT) {
            #pragma unroll
            for (int p = 0; p < 8; p++) {
                int idx = tid + p * 128;
                cp16(sm_u32(smq + ((t + 1) & 1) * 1024 + idx),
                     gK + (size_t)(t + 1) * 1024 + idx);
            }
        }
        #pragma unroll
        for (int p = 0; p < 8; p++) {
            int idx = tid + p * 128;
            cp16(sm_u32(smq + OVV + (t & 1) * 1024 + idx),
                 gV + (size_t)(idx >> 7) * 8192 + t * 128 + (idx & 127));
        }
        CP_COMMIT();

        const uint4* Kc = smq + (t & 1) * 1024;

        /* S(t) = Q K^T : warp m16 x n64, 8 k16-slices */
        float s[8][4] = {};
        #pragma unroll
        for (int ks = 0; ks < 8; ks++) {
            uint4 a = qr[ks];
            #pragma unroll
            for (int ni = 0; ni < 4; ni++) {
                uint4 KB = Kc[(ni * 8 + ks) * 32 + lane];
                mma8(s[2 * ni],     a, KB.x, KB.y);
                mma8(s[2 * ni + 1], a, KB.z, KB.w);
            }
        }

        /* PV(t-1): queued behind S(t); drains under the softmax below */
        if (t > 0) {
            const uint4* Vc = smq + OVV + ((t & 1) ^ 1) * 1024;
            #pragma unroll
            for (int ksj = 0; ksj < 4; ksj++) {
                uint4 a = pa[ksj];
                #pragma unroll
                for (int ni = 0; ni < 8; ni++) {
                    uint4 v = Vc[(ni * 4 + ksj) * 32 + lane];
                    mma8(o[2 * ni],     a, v.x, v.y);
                    mma8(o[2 * ni + 1], a, v.z, v.w);
                }
            }
        }

        /* softmax(t) in exp2 domain: fully warp-local */
        float mx0 = -1e30f, mx1 = -1e30f;
        #pragma unroll
        for (int nt = 0; nt < 8; nt++) {
            s[nt][0] = fmaf(mA[nt].x, LOG2E, s[nt][0]);
            s[nt][1] = fmaf(mA[nt].y, LOG2E, s[nt][1]);
            s[nt][2] = fmaf(mB[nt].x, LOG2E, s[nt][2]);
            s[nt][3] = fmaf(mB[nt].y, LOG2E, s[nt][3]);
            mx0 = fmaxf(mx0, fmaxf(s[nt][0], s[nt][1]));
            mx1 = fmaxf(mx1, fmaxf(s[nt][2], s[nt][3]));
        }
        mx0 = fmaxf(mx0, __shfl_xor_sync(0xffffffffu, mx0, 1));
        mx0 = fmaxf(mx0, __shfl_xor_sync(0xffffffffu, mx0, 2));
        mx1 = fmaxf(mx1, __shfl_xor_sync(0xffffffffu, mx1, 1));
        mx1 = fmaxf(mx1, __shfl_xor_sync(0xffffffffu, mx1, 2));
        float mn0 = fmaxf(m0, mx0);
        float mn1 = fmaxf(m1, mx1);

        float s0s = 0.f, s1s = 0.f;
        #pragma unroll
        for (int nt = 0; nt < 8; nt++) {
            s[nt][0] = exp2f(s[nt][0] - mn0);
            s[nt][1] = exp2f(s[nt][1] - mn0);
            s[nt][2] = exp2f(s[nt][2] - mn1);
            s[nt][3] = exp2f(s[nt][3] - mn1);
            s0s += s[nt][0] + s[nt][1];
            s1s += s[nt][2] + s[nt][3];
        }
        s0s += __shfl_xor_sync(0xffffffffu, s0s, 1);
        s0s += __shfl_xor_sync(0xffffffffu, s0s, 2);
        s1s += __shfl_xor_sync(0xffffffffu, s1s, 1);
        s1s += __shfl_xor_sync(0xffffffffu, s1s, 2);

        float sc0 = exp2f(m0 - mn0), sc1 = exp2f(m1 - mn1);
        l0 = l0 * sc0 + s0s;
        l1 = l1 * sc1 + s1s;
        m0 = mn0; m1 = mn1;
        #pragma unroll
        for (int nt = 0; nt < 16; nt++) {
            o[nt][0] *= sc0; o[nt][1] *= sc0;
            o[nt][2] *= sc1; o[nt][3] *= sc1;
        }

        /* pack P c-frags -> A-frags IN-LANE */
        #pragma unroll
        for (int KS = 0; KS < 4; KS++) {
            pa[KS].x = h2u(s[2 * KS][0],     s[2 * KS][1]);
            pa[KS].y = h2u(s[2 * KS][2],     s[2 * KS][3]);
            pa[KS].z = h2u(s[2 * KS + 1][0], s[2 * KS + 1][1]);
            pa[KS].w = h2u(s[2 * KS + 1][2], s[2 * KS + 1][3]);
        }
    }

    /* drain: PV(NT-1) */
    CP_WAIT(0);
    __syncthreads();
    {
        const uint4* Vc = smq + OVV + ((NT - 1) & 1) * 1024;
        #pragma unroll
        for (int ksj = 0; ksj < 4; ksj++) {
            uint4 a = pa[ksj];
            #pragma unroll
            for (int ni = 0; ni < 8; ni++) {
                uint4 v = Vc[(ni * 4 + ksj) * 32 + lane];
                mma8(o[2 * ni],     a, v.x, v.y);
                mma8(o[2 * ni + 1], a, v.z, v.w);
            }
        }
    }

    /* fused epilogue: normalize, stage f32, write fp16 A-frags to slot 5 */
    __syncthreads();
    float* St = (float*)smq;   /* 64 x 132 floats = 33.8 KB */
    {
        float inv0 = 1.f / l0, inv1 = 1.f / l1;
        #pragma unroll
        for (int nt = 0; nt < 16; nt++) {
            int c = nt * 8 + 2 * tg;
            St[R0 * 132 + c]     = o[nt][0] * inv0;
            St[R0 * 132 + c + 1] = o[nt][1] * inv0;
            St[R1 * 132 + c]     = o[nt][2] * inv1;
            St[R1 * 132 + c + 1] = o[nt][3] * inv1;
        }
    }
    __syncthreads();
    {
        uint4* gp5 = g_p + 5 * (size_t)SLOT_H;
        const int gMIb = b * 32 + qt * 4;   /* (b*TGT + qt*64)/16 */
        #pragma unroll
        for (int i = 0; i < 8; i++) {
            int MI = i >> 1;
            int ksl = wid * 2 + (i & 1);
            int r = MI * 16 + g, c = ksl * 16 + 2 * tg;
            uint4 u;
            u.x = h2u(St[r * 132 + c],           St[r * 132 + c + 1]);
            u.y = h2u(St[(r + 8) * 132 + c],     St[(r + 8) * 132 + c + 1]);
            u.z = h2u(St[r * 132 + c + 8],       St[r * 132 + c + 9]);
            u.w = h2u(St[(r + 8) * 132 + c + 8], St[(r + 8) * 132 + c + 9]);
            gp5[((size_t)(gMIb + MI) * 128 + (h * 8 + ksl)) * 32 + lane] = u;
        }
    }
}

/* ------------------------------------------------------------------ */
extern "C" void kernel_launch(void* const* d_in, const int* in_sizes, int n_in,
                              void* d_out, int out_size)
{
    const float* x       = (const float*)d_in[0];
    const float* k_cache = (const float*)d_in[1];
    const float* v_cache = (const float*)d_in[2];
    const float* mask    = (const float*)d_in[3];
    const float* wq = (const float*)d_in[4];
    const float* bq = (const float*)d_in[5];
    const float* wk = (const float*)d_in[6];
    const float* bk = (const float*)d_in[7];
    const float* wv = (const float*)d_in[8];
    const float* bv = (const float*)d_in[9];
    const float* wo = (const float*)d_in[10];
    const float* bo = (const float*)d_in[11];

    float* out = (float*)d_out;
    long long need = (long long)MROWS * EMB + 2LL * BSZ * KVLEN * EMB;
    int write_cache = ((long long)out_size >= need) ? 1 : 0;
    float* okc = out + (size_t)MROWS * EMB;
    float* ovc = okc + (size_t)BSZ * KVLEN * EMB;

    cudaFuncSetAttribute(attn_kernel,
                         cudaFuncAttributeMaxDynamicSharedMemorySize, ATT_SMEM);
    cudaFuncSetAttribute(qkv_kernel,
                         cudaFuncAttributeMaxDynamicSharedMemorySize, GEMM_SMEM);
    cudaFuncSetAttribute(proj_kernel,
                         cudaFuncAttributeMaxDynamicSharedMemorySize, GEMM_SMEM);

    convert5_kernel<<<dim3(2048, 5), 256>>>(x, wq, wk, wv, wo);
    qkv_kernel<<<dim3(96, 16), 256, GEMM_SMEM>>>(k_cache, v_cache,
                                                 bq, bk, bv, okc, ovc, write_cache);
    permute_new_kernel<<<1024, 256>>>();
    attn_kernel<<<dim3(8, 16, BSZ + 1), 128, ATT_SMEM>>>(k_cache, v_cache, mask,
                                                         okc, ovc, write_cache);
    proj_kernel<<<dim3(16, 16), 256, GEMM_SMEM>>>(bo, out);
}

// round 16
// speedup vs baseline: 1.8861x; 1.0851x over previous
#include <cuda_runtime.h>
#include <cuda_fp16.h>

#define BSZ   4
#define TGT   512
#define KVLEN 4096
#define KVOLD (KVLEN - TGT)   /* 3584 */
#define EMB   2048
#define NH    16
#define HD    128
#define MROWS (BSZ * TGT)     /* 2048 */
#define SLOT_H 524288         /* uint4 per fp16-permuted 2048x2048 matrix */
#define QSCALE 0.08838834764831845f  /* 128^-0.5 */
#define LOG2E  1.4426950408889634f
#define QS2    (QSCALE * LOG2E)      /* folded: softmax runs in exp2 domain */

/* scratch (static device arrays: allocation-free per harness rules) */
__device__ float g_q[MROWS * EMB];
__device__ float g_k[MROWS * EMB];
__device__ float g_v[MROWS * EMB];
/* permuted fp16 operands: 0=x(A) 1=wq(B) 2=wk(B) 3=wv(B) 4=wo(B) 5=attn(A) */
__device__ uint4 g_p[6 * SLOT_H];                /* 48 MB */
/* permuted fp16 KV cache, fragment layout, per (b,h): 65536 uint4 */
__device__ uint4 g_kp[64 * 65536];               /* 64 MB */
__device__ uint4 g_vp[64 * 65536];               /* 64 MB */
/* mask-nonzero flag (set by mask_scan each launch) */
__device__ int g_mask_nz;

/* ---------------- helpers ---------------- */
__device__ __forceinline__ unsigned h2u(float lo, float hi) {
    unsigned u;
    asm("cvt.rn.f16x2.f32 %0, %1, %2;" : "=r"(u) : "f"(hi), "f"(lo));
    return u;
}
__device__ __forceinline__ void mma8(float c[4], const uint4& a, unsigned b0, unsigned b1) {
    asm("mma.sync.aligned.m16n8k16.row.col.f32.f16.f16.f32 "
        "{%0,%1,%2,%3},{%4,%5,%6,%7},{%8,%9},{%0,%1,%2,%3};"
        : "+f"(c[0]), "+f"(c[1]), "+f"(c[2]), "+f"(c[3])
        : "r"(a.x), "r"(a.y), "r"(a.z), "r"(a.w), "r"(b0), "r"(b1));
}
__device__ __forceinline__ unsigned sm_u32(const void* p) {
    return (unsigned)__cvta_generic_to_shared(p);
}
__device__ __forceinline__ void cp16(unsigned dst, const void* src) {
    asm volatile("cp.async.cg.shared.global [%0], [%1], 16;" :: "r"(dst), "l"(src));
}
#define CP_COMMIT() asm volatile("cp.async.commit_group;")
#define CP_WAIT(n)  asm volatile("cp.async.wait_group %0;" :: "n"(n))

/* ---------------- mask-zero detection ---------------- */
__global__ void flag_init_kernel() { g_mask_nz = 0; }

__global__ void __launch_bounds__(256) mask_scan_kernel(const float* __restrict__ mask)
{
    /* mask has TGT*KVLEN = 2M floats = 524288 float4; grid 512 x 256 thr x 4 f4 */
    size_t base = ((size_t)blockIdx.x * 256 + threadIdx.x) * 4;
    const float4* m4 = (const float4*)mask;
    int nz = 0;
    #pragma unroll
    for (int i = 0; i < 4; i++) {
        float4 v = m4[base + i];
        nz |= (v.x != 0.f) | (v.y != 0.f) | (v.z != 0.f) | (v.w != 0.f);
    }
    if (__syncthreads_or(nz)) {
        if (threadIdx.x == 0) atomicExch(&g_mask_nz, 1);
    }
}

/* ---------------- dense-operand permute (fp16 A/B fragment layouts) ---------- */
__device__ __forceinline__ void permute_one(const float* __restrict__ src,
                                            uint4* __restrict__ dst,
                                            unsigned gid, int btype)
{
    unsigned lane = gid & 31, KS = (gid >> 5) & 127, MI = gid >> 12;
    unsigned g = lane >> 2, tg = lane & 3;
    const float* p = src + (size_t)(MI * 16 + g) * EMB + KS * 16 + 2 * tg;
    float2 v0 = *(const float2*)(p);
    float2 v1 = *(const float2*)(p + 8 * EMB);
    float2 v2 = *(const float2*)(p + 8);
    float2 v3 = *(const float2*)(p + 8 * EMB + 8);
    uint4 u;
    if (btype) {
        u.x = h2u(v0.x, v0.y); u.y = h2u(v2.x, v2.y);
        u.z = h2u(v1.x, v1.y); u.w = h2u(v3.x, v3.y);
    } else {
        u.x = h2u(v0.x, v0.y); u.y = h2u(v1.x, v1.y);
        u.z = h2u(v2.x, v2.y); u.w = h2u(v3.x, v3.y);
    }
    dst[gid] = u;
}

__global__ void __launch_bounds__(256) convert5_kernel(
    const float* __restrict__ x,  const float* __restrict__ wq,
    const float* __restrict__ wk, const float* __restrict__ wv,
    const float* __restrict__ wo)
{
    int slot = blockIdx.y;
    const float* src = (slot == 0) ? x : (slot == 1) ? wq :
                       (slot == 2) ? wk : (slot == 3) ? wv : wo;
    unsigned gid = blockIdx.x * 256 + threadIdx.x;
    permute_one(src, g_p + (size_t)slot * SLOT_H, gid, slot != 0);
}

/* ---------------- KV tile permute (64 j x 128 d staged in smem, fp16 out) ---- */
__device__ __forceinline__ void kv_permute_tile(
    const float* __restrict__ src, float* Ts, int tt, int bh, int isV, int tid)
{
    const int lane = tid & 31, g = lane >> 2, tg = lane & 3;
    __syncthreads();
    #pragma unroll
    for (int p = 0; p < 8; p++) {
        int idx = tid + p * 256;
        int r = idx >> 5, c4 = (idx & 31) << 2;
        *(float4*)&Ts[r * 132 + c4] = *(const float4*)(src + (size_t)r * EMB + c4);
    }
    __syncthreads();
    if (!isV) {
        uint4* dst = g_kp + (size_t)bh * 65536 + (size_t)tt * 1024;
        #pragma unroll
        for (int p = 0; p < 4; p++) {
            int idx = tid + p * 256;                 /* (NI*8+KS)*32+lane */
            int KS = (idx >> 5) & 7, NI = idx >> 8;
            int j = NI * 16 + g, d = KS * 16 + 2 * tg;
            uint4 u;
            u.x = h2u(Ts[j * 132 + d],           Ts[j * 132 + d + 1]);
            u.y = h2u(Ts[j * 132 + d + 8],       Ts[j * 132 + d + 9]);
            u.z = h2u(Ts[(j + 8) * 132 + d],     Ts[(j + 8) * 132 + d + 1]);
            u.w = h2u(Ts[(j + 8) * 132 + d + 8], Ts[(j + 8) * 132 + d + 9]);
            dst[idx] = u;
        }
    } else {
        uint4* dst = g_vp + (size_t)bh * 65536;
        #pragma unroll
        for (int p = 0; p < 4; p++) {
            int idx = tid + p * 256;                 /* NI*128 + KSj*32 + lane */
            int KSj = (idx >> 5) & 3, NI = idx >> 7;
            int j = KSj * 16 + 2 * tg, d = NI * 16 + g;
            uint4 u;
            u.x = h2u(Ts[j * 132 + d],           Ts[(j + 1) * 132 + d]);
            u.y = h2u(Ts[(j + 8) * 132 + d],     Ts[(j + 9) * 132 + d]);
            u.z = h2u(Ts[j * 132 + d + 8],       Ts[(j + 1) * 132 + d + 8]);
            u.w = h2u(Ts[(j + 8) * 132 + d + 8], Ts[(j + 9) * 132 + d + 8]);
            dst[(size_t)NI * 8192 + (tt * 4 + KSj) * 32 + (idx & 31)] = u;
        }
    }
}

/* permute NEW kv region (from g_k/g_v). 1024 blocks. */
__global__ void __launch_bounds__(256) permute_new_kernel()
{
    __shared__ float Ts[64 * 132];
    int job = blockIdx.x;
    int isV = job >= 512;
    int jj = job & 511;
    int bh = jj >> 3, tl = jj & 7;
    int b = bh >> 4, h = bh & 15;
    const float* src = (isV ? g_v : g_k) + ((size_t)(b * TGT) + tl * 64) * EMB + h * HD;
    kv_permute_tile(src, Ts, 56 + tl, bh, isV, threadIdx.x);
}

/* ---------------- dense GEMM: C[128,128] = A @ B^T, fp16 fragments ---------- */
#define GSTG 1024
#define GEMM_SMEM (3 * GSTG * 16)

__device__ __forceinline__ void gemm_main(
    const uint4* __restrict__ Ag, const uint4* __restrict__ Bg,
    float c[4][4][4], uint4* S, int tid)
{
    const int lane = tid & 31, wid = tid >> 5;
    const int wm = wid >> 2, wn = wid & 3;

    #pragma unroll
    for (int st = 0; st < 2; st++) {
        #pragma unroll
        for (int i = 0; i < 4; i++) {
            int ch = tid + i * 256;
            int half = ch >> 9, cc = ch & 511;
            int mi = cc >> 6, ksl = (cc >> 5) & 1, l = cc & 31;
            const uint4* src = (half ? Bg : Ag)
                + (size_t)mi * 4096 + (2 * st + ksl) * 32 + l;
            cp16(sm_u32(S + st * GSTG + half * 512 + cc), src);
        }
        CP_COMMIT();
    }

    for (int kt = 0; kt < 64; kt++) {
        if (kt < 63) CP_WAIT(1); else CP_WAIT(0);
        __syncthreads();

        if (kt + 2 < 64) {
            int st = (kt + 2) % 3;
            #pragma unroll
            for (int i = 0; i < 4; i++) {
                int ch = tid + i * 256;
                int half = ch >> 9, cc = ch & 511;
                int mi = cc >> 6, ksl = (cc >> 5) & 1, l = cc & 31;
                const uint4* src = (half ? Bg : Ag)
                    + (size_t)mi * 4096 + (2 * (kt + 2) + ksl) * 32 + l;
                cp16(sm_u32(S + st * GSTG + half * 512 + cc), src);
            }
            CP_COMMIT();
        }

        const uint4* Af = S + (kt % 3) * GSTG;
        const uint4* Bf = Af + 512;
        #pragma unroll
        for (int ks = 0; ks < 2; ks++) {
            uint4 a[4], bu[2];
            #pragma unroll
            for (int mt = 0; mt < 4; mt++)
                a[mt] = Af[((wm * 4 + mt) * 2 + ks) * 32 + lane];
            #pragma unroll
            for (int p = 0; p < 2; p++)
                bu[p] = Bf[((wn * 2 + p) * 2 + ks) * 32 + lane];
            #pragma unroll
            for (int mt = 0; mt < 4; mt++) {
                mma8(c[mt][0], a[mt], bu[0].x, bu[0].y);
                mma8(c[mt][1], a[mt], bu[0].z, bu[0].w);
                mma8(c[mt][2], a[mt], bu[1].x, bu[1].y);
                mma8(c[mt][3], a[mt], bu[1].z, bu[1].w);
            }
        }
    }
}

/* Fused QKV + interleaved old-KV permute plane. grid (96,16). */
__global__ void __launch_bounds__(256, 2) qkv_kernel(
    const float* __restrict__ kc_in, const float* __restrict__ vc_in,
    const float* __restrict__ bq, const float* __restrict__ bk,
    const float* __restrict__ bv,
    float* __restrict__ okc, float* __restrict__ ovc, int write_cache)
{
    extern __shared__ uint4 S[];
    const int tid = threadIdx.x;

    if (blockIdx.x >= 48) {
        float* Ts = (float*)S;
        int pbid = (blockIdx.x - 48) + 48 * blockIdx.y;
        for (int job = pbid; job < 7168; job += 768) {
            int isV = job >= 3584;
            int jj = isV ? job - 3584 : job;
            int bh = jj / 56, tt = jj % 56;
            int b = bh >> 4, h = bh & 15;
            const float* src = (isV ? vc_in : kc_in)
                + ((size_t)(b * KVLEN) + tt * 64) * EMB + h * HD;
            kv_permute_tile(src, Ts, tt, bh, isV, tid);
        }
        return;
    }

    const int lane = tid & 31, wid = tid >> 5;
    const int g = lane >> 2, tg = lane & 3;
    const int wm = wid >> 2, wn = wid & 3;
    const int nb = blockIdx.x, mb = blockIdx.y;
    const int sel = nb >> 4, nblk = nb & 15;
    const float* bias = (sel == 0) ? bq : (sel == 1) ? bk : bv;

    const uint4* Ag = g_p + (size_t)mb * 32768;
    const uint4* Bg = g_p + (size_t)(1 + sel) * SLOT_H + (size_t)nblk * 32768;

    float c[4][4][4] = {};
    gemm_main(Ag, Bg, c, S, tid);

    #pragma unroll
    for (int mt = 0; mt < 4; mt++) {
        #pragma unroll
        for (int nt = 0; nt < 4; nt++) {
            int col = nblk * 128 + wn * 32 + nt * 8 + 2 * tg;
            #pragma unroll
            for (int half = 0; half < 2; half++) {
                int m = mb * 128 + wm * 64 + mt * 16 + g + half * 8;
                float v0 = c[mt][nt][half * 2 + 0] + bias[col];
                float v1 = c[mt][nt][half * 2 + 1] + bias[col + 1];
                if (sel == 0) {
                    g_q[(size_t)m * EMB + col]     = v0 * QS2;
                    g_q[(size_t)m * EMB + col + 1] = v1 * QS2;
                } else {
                    float* dst = (sel == 1) ? g_k : g_v;
                    dst[(size_t)m * EMB + col]     = v0;
                    dst[(size_t)m * EMB + col + 1] = v1;
                    if (write_cache) {
                        int bidx = m >> 9, t = m & 511;
                        float* cd = (sel == 1) ? okc : ovc;
                        size_t o = ((size_t)bidx * KVLEN + KVOLD + t) * EMB + col;
                        cd[o] = v0; cd[o + 1] = v1;
                    }
                }
            }
        }
    }
}

/* Output projection: grid (16,16). A = fp16-permuted attn (slot 5). */
__global__ void __launch_bounds__(256, 2) proj_kernel(
    const float* __restrict__ bo, float* __restrict__ out)
{
    extern __shared__ uint4 S[];
    const int tid = threadIdx.x;
    const int lane = tid & 31, wid = tid >> 5;
    const int g = lane >> 2, tg = lane & 3;
    const int wm = wid >> 2, wn = wid & 3;
    const int nblk = blockIdx.x, mb = blockIdx.y;

    const uint4* Ag = g_p + 5 * (size_t)SLOT_H + (size_t)mb * 32768;
    const uint4* Bg = g_p + 4 * (size_t)SLOT_H + (size_t)nblk * 32768;

    float c[4][4][4] = {};
    gemm_main(Ag, Bg, c, S, tid);

    #pragma unroll
    for (int mt = 0; mt < 4; mt++)
        #pragma unroll
        for (int nt = 0; nt < 4; nt++) {
            int col = nblk * 128 + wn * 32 + nt * 8 + 2 * tg;
            #pragma unroll
            for (int half = 0; half < 2; half++) {
                int m = mb * 128 + wm * 64 + mt * 16 + g + half * 8;
                out[(size_t)m * EMB + col]     = c[mt][nt][half * 2 + 0] + bo[col];
                out[(size_t)m * EMB + col + 1] = c[mt][nt][half * 2 + 1] + bo[col + 1];
            }
        }
}

/* ---------------- flash attention: 2 small CTAs/SM, exp2, mask fast path ----
   128 thr, 4 warps; warp w owns rows [w*16, w*16+16) x ALL 64 KV cols.
   g_mask_nz==0 (detected at runtime) -> skip ALL mask loads and FMAs:
   saves 512 MB of L2->L1 traffic and 16 LDG + 32 FMA per warp per tile.
   Nonzero path identical to round 15.                                        */
#define OVV 2048
#define ATT_SMEM (4096 * 16)
#define NT (KVLEN / 64)

__global__ void __launch_bounds__(128, 2) attn_kernel(
    const float* __restrict__ kc_in, const float* __restrict__ vc_in,
    const float* __restrict__ mask,
    float* __restrict__ okc, float* __restrict__ ovc, int write_cache)
{
    if (blockIdx.z == BSZ) {
        if (write_cache) {
            const int cb = blockIdx.x + gridDim.x * blockIdx.y;   /* 0..127 */
            const int N4 = KVOLD * EMB / 4;
            #pragma unroll 1
            for (int b = 0; b < BSZ; b++) {
                const float4* sk = (const float4*)(kc_in + (size_t)b * KVLEN * EMB);
                const float4* sv = (const float4*)(vc_in + (size_t)b * KVLEN * EMB);
                float4* dk = (float4*)(okc + (size_t)b * KVLEN * EMB);
                float4* dv = (float4*)(ovc + (size_t)b * KVLEN * EMB);
                for (int i = cb * 128 + (int)threadIdx.x; i < N4; i += 128 * 128) {
                    dk[i] = sk[i];
                    dv[i] = sv[i];
                }
            }
        }
        return;
    }

    extern __shared__ uint4 smq[];

    const int tid  = threadIdx.x;
    const int lane = tid & 31, wid = tid >> 5;          /* wid 0..3 */
    const int g = lane >> 2, tg = lane & 3;
    const int qt = blockIdx.x, h = blockIdx.y, b = blockIdx.z;
    const int mnz = g_mask_nz;                          /* uniform */

    const uint4* gK = g_kp + (size_t)(b * 16 + h) * 65536;
    const uint4* gV = g_vp + (size_t)(b * 16 + h) * 65536;
    const int R0 = wid * 16 + g;
    const int R1 = R0 + 8;
    const float* mrow0 = mask + (size_t)(qt * 64 + R0) * KVLEN;
    const float* mrow1 = mask + (size_t)(qt * 64 + R1) * KVLEN;

    /* prologue: K(0) */
    #pragma unroll
    for (int p = 0; p < 8; p++) {
        int idx = tid + p * 128;
        cp16(sm_u32(smq + idx), gK + idx);
    }
    CP_COMMIT();

    /* Q A-frags in registers (already scaled by QSCALE*log2e) */
    uint4 qr[8];
    {
        const float* qb = g_q + (size_t)(b * TGT + qt * 64 + wid * 16 + g) * EMB + h * HD;
        #pragma unroll
        for (int ks = 0; ks < 8; ks++) {
            const float* p = qb + ks * 16 + 2 * tg;
            float2 v0 = *(const float2*)(p);
            float2 v1 = *(const float2*)(p + 8 * EMB);
            float2 v2 = *(const float2*)(p + 8);
            float2 v3 = *(const float2*)(p + 8 * EMB + 8);
            qr[ks].x = h2u(v0.x, v0.y); qr[ks].y = h2u(v1.x, v1.y);
            qr[ks].z = h2u(v2.x, v2.y); qr[ks].w = h2u(v3.x, v3.y);
        }
    }

    float m0 = -1e30f, m1 = -1e30f, l0 = 0.f, l1 = 0.f;
    float o[16][4] = {};
    uint4 pa[4];   /* deferred P A-frags (previous tile) */

    #pragma unroll 1
    for (int t = 0; t < NT; t++) {
        /* mask prefetch (only when mask is nonzero anywhere) */
        float2 mA[8], mB[8];
        if (mnz) {
            #pragma unroll
            for (int nt = 0; nt < 8; nt++) {
                int col = t * 64 + nt * 8 + 2 * tg;
                mA[nt] = *(const float2*)(mrow0 + col);
                mB[nt] = *(const float2*)(mrow1 + col);
            }
        }

        CP_WAIT(0);          /* group(t-1): K(t) + V(t-1) ready */
        __syncthreads();

        /* issue group(t): K(t+1), V(t) */
        if (t + 1 < NT) {
            #pragma unroll
            for (int p = 0; p < 8; p++) {
                int idx = tid + p * 128;
                cp16(sm_u32(smq + ((t + 1) & 1) * 1024 + idx),
                     gK + (size_t)(t + 1) * 1024 + idx);
            }
        }
        #pragma unroll
        for (int p = 0; p < 8; p++) {
            int idx = tid + p * 128;
            cp16(sm_u32(smq + OVV + (t & 1) * 1024 + idx),
                 gV + (size_t)(idx >> 7) * 8192 + t * 128 + (idx & 127));
        }
        CP_COMMIT();

        const uint4* Kc = smq + (t & 1) * 1024;

        /* S(t) = Q K^T : warp m16 x n64, 8 k16-slices */
        float s[8][4] = {};
        #pragma unroll
        for (int ks = 0; ks < 8; ks++) {
            uint4 a = qr[ks];
            #pragma unroll
            for (int ni = 0; ni < 4; ni++) {
                uint4 KB = Kc[(ni * 8 + ks) * 32 + lane];
                mma8(s[2 * ni],     a, KB.x, KB.y);
                mma8(s[2 * ni + 1], a, KB.z, KB.w);
            }
        }

        /* PV(t-1): queued behind S(t); drains under the softmax below */
        if (t > 0) {
            const uint4* Vc = smq + OVV + ((t & 1) ^ 1) * 1024;
            #pragma unroll
            for (int ksj = 0; ksj < 4; ksj++) {
                uint4 a = pa[ksj];
                #pragma unroll
                for (int ni = 0; ni < 8; ni++) {
                    uint4 v = Vc[(ni * 4 + ksj) * 32 + lane];
                    mma8(o[2 * ni],     a, v.x, v.y);
                    mma8(o[2 * ni + 1], a, v.z, v.w);
                }
            }
        }

        /* softmax(t) in exp2 domain: fully warp-local */
        if (mnz) {
            #pragma unroll
            for (int nt = 0; nt < 8; nt++) {
                s[nt][0] = fmaf(mA[nt].x, LOG2E, s[nt][0]);
                s[nt][1] = fmaf(mA[nt].y, LOG2E, s[nt][1]);
                s[nt][2] = fmaf(mB[nt].x, LOG2E, s[nt][2]);
                s[nt][3] = fmaf(mB[nt].y, LOG2E, s[nt][3]);
            }
        }
        float mx0 = -1e30f, mx1 = -1e30f;
        #pragma unroll
        for (int nt = 0; nt < 8; nt++) {
            mx0 = fmaxf(mx0, fmaxf(s[nt][0], s[nt][1]));
            mx1 = fmaxf(mx1, fmaxf(s[nt][2], s[nt][3]));
        }
        mx0 = fmaxf(mx0, __shfl_xor_sync(0xffffffffu, mx0, 1));
        mx0 = fmaxf(mx0, __shfl_xor_sync(0xffffffffu, mx0, 2));
        mx1 = fmaxf(mx1, __shfl_xor_sync(0xffffffffu, mx1, 1));
        mx1 = fmaxf(mx1, __shfl_xor_sync(0xffffffffu, mx1, 2));
        float mn0 = fmaxf(m0, mx0);
        float mn1 = fmaxf(m1, mx1);

        float s0s = 0.f, s1s = 0.f;
        #pragma unroll
        for (int nt = 0; nt < 8; nt++) {
            s[nt][0] = exp2f(s[nt][0] - mn0);
            s[nt][1] = exp2f(s[nt][1] - mn0);
            s[nt][2] = exp2f(s[nt][2] - mn1);
            s[nt][3] = exp2f(s[nt][3] - mn1);
            s0s += s[nt][0] + s[nt][1];
            s1s += s[nt][2] + s[nt][3];
        }
        s0s += __shfl_xor_sync(0xffffffffu, s0s, 1);
        s0s += __shfl_xor_sync(0xffffffffu, s0s, 2);
        s1s += __shfl_xor_sync(0xffffffffu, s1s, 1);
        s1s += __shfl_xor_sync(0xffffffffu, s1s, 2);

        float sc0 = exp2f(m0 - mn0), sc1 = exp2f(m1 - mn1);
        l0 = l0 * sc0 + s0s;
        l1 = l1 * sc1 + s1s;
        m0 = mn0; m1 = mn1;
        #pragma unroll
        for (int nt = 0; nt < 16; nt++) {
            o[nt][0] *= sc0; o[nt][1] *= sc0;
            o[nt][2] *= sc1; o[nt][3] *= sc1;
        }

        /* pack P c-frags -> A-frags IN-LANE */
        #pragma unroll
        for (int KS = 0; KS < 4; KS++) {
            pa[KS].x = h2u(s[2 * KS][0],     s[2 * KS][1]);
            pa[KS].y = h2u(s[2 * KS][2],     s[2 * KS][3]);
            pa[KS].z = h2u(s[2 * KS + 1][0], s[2 * KS + 1][1]);
            pa[KS].w = h2u(s[2 * KS + 1][2], s[2 * KS + 1][3]);
        }
    }

    /* drain: PV(NT-1) */
    CP_WAIT(0);
    __syncthreads();
    {
        const uint4* Vc = smq + OVV + ((NT - 1) & 1) * 1024;
        #pragma unroll
        for (int ksj = 0; ksj < 4; ksj++) {
            uint4 a = pa[ksj];
            #pragma unroll
            for (int ni = 0; ni < 8; ni++) {
                uint4 v = Vc[(ni * 4 + ksj) * 32 + lane];
                mma8(o[2 * ni],     a, v.x, v.y);
                mma8(o[2 * ni + 1], a, v.z, v.w);
            }
        }
    }

    /* fused epilogue: normalize, stage f32, write fp16 A-frags to slot 5 */
    __syncthreads();
    float* St = (float*)smq;   /* 64 x 132 floats = 33.8 KB */
    {
        float inv0 = 1.f / l0, inv1 = 1.f / l1;
        #pragma unroll
        for (int nt = 0; nt < 16; nt++) {
            int c = nt * 8 + 2 * tg;
            St[R0 * 132 + c]     = o[nt][0] * inv0;
            St[R0 * 132 + c + 1] = o[nt][1] * inv0;
            St[R1 * 132 + c]     = o[nt][2] * inv1;
            St[R1 * 132 + c + 1] = o[nt][3] * inv1;
        }
    }
    __syncthreads();
    {
        uint4* gp5 = g_p + 5 * (size_t)SLOT_H;
        const int gMIb = b * 32 + qt * 4;   /* (b*TGT + qt*64)/16 */
        #pragma unroll
        for (int i = 0; i < 8; i++) {
            int MI = i >> 1;
            int ksl = wid * 2 + (i & 1);
            int r = MI * 16 + g, c = ksl * 16 + 2 * tg;
            uint4 u;
            u.x = h2u(St[r * 132 + c],           St[r * 132 + c + 1]);
            u.y = h2u(St[(r + 8) * 132 + c],     St[(r + 8) * 132 + c + 1]);
            u.z = h2u(St[r * 132 + c + 8],       St[r * 132 + c + 9]);
            u.w = h2u(St[(r + 8) * 132 + c + 8], St[(r + 8) * 132 + c + 9]);
            gp5[((size_t)(gMIb + MI) * 128 + (h * 8 + ksl)) * 32 + lane] = u;
        }
    }
}

/* ------------------------------------------------------------------ */
extern "C" void kernel_launch(void* const* d_in, const int* in_sizes, int n_in,
                              void* d_out, int out_size)
{
    const float* x       = (const float*)d_in[0];
    const float* k_cache = (const float*)d_in[1];
    const float* v_cache = (const float*)d_in[2];
    const float* mask    = (const float*)d_in[3];
    const float* wq = (const float*)d_in[4];
    const float* bq = (const float*)d_in[5];
    const float* wk = (const float*)d_in[6];
    const float* bk = (const float*)d_in[7];
    const float* wv = (const float*)d_in[8];
    const float* bv = (const float*)d_in[9];
    const float* wo = (const float*)d_in[10];
    const float* bo = (const float*)d_in[11];

    float* out = (float*)d_out;
    long long need = (long long)MROWS * EMB + 2LL * BSZ * KVLEN * EMB;
    int write_cache = ((long long)out_size >= need) ? 1 : 0;
    float* okc = out + (size_t)MROWS * EMB;
    float* ovc = okc + (size_t)BSZ * KVLEN * EMB;

    cudaFuncSetAttribute(attn_kernel,
                         cudaFuncAttributeMaxDynamicSharedMemorySize, ATT_SMEM);
    cudaFuncSetAttribute(qkv_kernel,
                         cudaFuncAttributeMaxDynamicSharedMemorySize, GEMM_SMEM);
    cudaFuncSetAttribute(proj_kernel,
                         cudaFuncAttributeMaxDynamicSharedMemorySize, GEMM_SMEM);

    flag_init_kernel<<<1, 1>>>();
    mask_scan_kernel<<<512, 256>>>(mask);
    convert5_kernel<<<dim3(2048, 5), 256>>>(x, wq, wk, wv, wo);
    qkv_kernel<<<dim3(96, 16), 256, GEMM_SMEM>>>(k_cache, v_cache,
                                                 bq, bk, bv, okc, ovc, write_cache);
    permute_new_kernel<<<1024, 256>>>();
    attn_kernel<<<dim3(8, 16, BSZ + 1), 128, ATT_SMEM>>>(k_cache, v_cache, mask,
                                                         okc, ovc, write_cache);
    proj_kernel<<<dim3(16, 16), 256, GEMM_SMEM>>>(bo, out);
}

// round 17
// speedup vs baseline: 2.0290x; 1.0758x over previous
#include <cuda_runtime.h>
#include <cuda_fp16.h>

#define BSZ   4
#define TGT   512
#define KVLEN 4096
#define KVOLD (KVLEN - TGT)   /* 3584 */
#define EMB   2048
#define NH    16
#define HD    128
#define MROWS (BSZ * TGT)     /* 2048 */
#define SLOT_H 524288         /* uint4 per fp16-permuted 2048x2048 matrix */
#define QSCALE 0.08838834764831845f  /* 128^-0.5 */
#define LOG2E  1.4426950408889634f
#define QS2    (QSCALE * LOG2E)      /* folded: softmax runs in exp2 domain */

/* scratch (static device arrays: allocation-free per harness rules) */
__device__ float g_q[MROWS * EMB];
__device__ float g_k[MROWS * EMB];
__device__ float g_v[MROWS * EMB];
/* permuted fp16 operands: 0=x(A) 1=wq(B) 2=wk(B) 3=wv(B) 4=wo(B) 5=attn(A) */
__device__ uint4 g_p[6 * SLOT_H];                /* 48 MB */
/* permuted fp16 KV cache, fragment layout, per (b,h): 65536 uint4 */
__device__ uint4 g_kp[64 * 65536];               /* 64 MB */
__device__ uint4 g_vp[64 * 65536];               /* 64 MB */
/* mask-nonzero flag (set by mask_scan each launch) */
__device__ int g_mask_nz;

/* ---------------- helpers ---------------- */
__device__ __forceinline__ unsigned h2u(float lo, float hi) {
    unsigned u;
    asm("cvt.rn.f16x2.f32 %0, %1, %2;" : "=r"(u) : "f"(hi), "f"(lo));
    return u;
}
__device__ __forceinline__ void mma8(float c[4], const uint4& a, unsigned b0, unsigned b1) {
    asm("mma.sync.aligned.m16n8k16.row.col.f32.f16.f16.f32 "
        "{%0,%1,%2,%3},{%4,%5,%6,%7},{%8,%9},{%0,%1,%2,%3};"
        : "+f"(c[0]), "+f"(c[1]), "+f"(c[2]), "+f"(c[3])
        : "r"(a.x), "r"(a.y), "r"(a.z), "r"(a.w), "r"(b0), "r"(b1));
}
__device__ __forceinline__ unsigned sm_u32(const void* p) {
    return (unsigned)__cvta_generic_to_shared(p);
}
__device__ __forceinline__ void cp16(unsigned dst, const void* src) {
    asm volatile("cp.async.cg.shared.global [%0], [%1], 16;" :: "r"(dst), "l"(src));
}
#define CP_COMMIT() asm volatile("cp.async.commit_group;")
#define CP_WAIT(n)  asm volatile("cp.async.wait_group %0;" :: "n"(n))

/* ---------------- mask-zero detection ---------------- */
__global__ void flag_init_kernel() { g_mask_nz = 0; }

__global__ void __launch_bounds__(256) mask_scan_kernel(const float* __restrict__ mask)
{
    size_t base = ((size_t)blockIdx.x * 256 + threadIdx.x) * 4;
    const float4* m4 = (const float4*)mask;
    int nz = 0;
    #pragma unroll
    for (int i = 0; i < 4; i++) {
        float4 v = m4[base + i];
        nz |= (v.x != 0.f) | (v.y != 0.f) | (v.z != 0.f) | (v.w != 0.f);
    }
    if (__syncthreads_or(nz)) {
        if (threadIdx.x == 0) atomicExch(&g_mask_nz, 1);
    }
}

/* ---------------- dense-operand permute (fp16 A/B fragment layouts) ---------- */
__device__ __forceinline__ void permute_one(const float* __restrict__ src,
                                            uint4* __restrict__ dst,
                                            unsigned gid, int btype)
{
    unsigned lane = gid & 31, KS = (gid >> 5) & 127, MI = gid >> 12;
    unsigned g = lane >> 2, tg = lane & 3;
    const float* p = src + (size_t)(MI * 16 + g) * EMB + KS * 16 + 2 * tg;
    float2 v0 = *(const float2*)(p);
    float2 v1 = *(const float2*)(p + 8 * EMB);
    float2 v2 = *(const float2*)(p + 8);
    float2 v3 = *(const float2*)(p + 8 * EMB + 8);
    uint4 u;
    if (btype) {
        u.x = h2u(v0.x, v0.y); u.y = h2u(v2.x, v2.y);
        u.z = h2u(v1.x, v1.y); u.w = h2u(v3.x, v3.y);
    } else {
        u.x = h2u(v0.x, v0.y); u.y = h2u(v1.x, v1.y);
        u.z = h2u(v2.x, v2.y); u.w = h2u(v3.x, v3.y);
    }
    dst[gid] = u;
}

__global__ void __launch_bounds__(256) convert5_kernel(
    const float* __restrict__ x,  const float* __restrict__ wq,
    const float* __restrict__ wk, const float* __restrict__ wv,
    const float* __restrict__ wo)
{
    int slot = blockIdx.y;
    const float* src = (slot == 0) ? x : (slot == 1) ? wq :
                       (slot == 2) ? wk : (slot == 3) ? wv : wo;
    unsigned gid = blockIdx.x * 256 + threadIdx.x;
    permute_one(src, g_p + (size_t)slot * SLOT_H, gid, slot != 0);
}

/* ---------------- KV tile permute (64 j x 128 d staged in smem, fp16 out) ----
   Optionally also writes the fp32 copy-out (cache splice) from the staged
   read: single DRAM read serves both the permuted fp16 and the fp32 copy.   */
__device__ __forceinline__ void kv_permute_tile(
    const float* __restrict__ src, float* __restrict__ cpy,
    float* Ts, int tt, int bh, int isV, int tid)
{
    const int lane = tid & 31, g = lane >> 2, tg = lane & 3;
    __syncthreads();
    #pragma unroll
    for (int p = 0; p < 8; p++) {
        int idx = tid + p * 256;
        int r = idx >> 5, c4 = (idx & 31) << 2;
        float4 v = *(const float4*)(src + (size_t)r * EMB + c4);
        *(float4*)&Ts[r * 132 + c4] = v;
        if (cpy) *(float4*)(cpy + (size_t)r * EMB + c4) = v;
    }
    __syncthreads();
    if (!isV) {
        uint4* dst = g_kp + (size_t)bh * 65536 + (size_t)tt * 1024;
        #pragma unroll
        for (int p = 0; p < 4; p++) {
            int idx = tid + p * 256;                 /* (NI*8+KS)*32+lane */
            int KS = (idx >> 5) & 7, NI = idx >> 8;
            int j = NI * 16 + g, d = KS * 16 + 2 * tg;
            uint4 u;
            u.x = h2u(Ts[j * 132 + d],           Ts[j * 132 + d + 1]);
            u.y = h2u(Ts[j * 132 + d + 8],       Ts[j * 132 + d + 9]);
            u.z = h2u(Ts[(j + 8) * 132 + d],     Ts[(j + 8) * 132 + d + 1]);
            u.w = h2u(Ts[(j + 8) * 132 + d + 8], Ts[(j + 8) * 132 + d + 9]);
            dst[idx] = u;
        }
    } else {
        uint4* dst = g_vp + (size_t)bh * 65536;
        #pragma unroll
        for (int p = 0; p < 4; p++) {
            int idx = tid + p * 256;                 /* NI*128 + KSj*32 + lane */
            int KSj = (idx >> 5) & 3, NI = idx >> 7;
            int j = KSj * 16 + 2 * tg, d = NI * 16 + g;
            uint4 u;
            u.x = h2u(Ts[j * 132 + d],           Ts[(j + 1) * 132 + d]);
            u.y = h2u(Ts[(j + 8) * 132 + d],     Ts[(j + 9) * 132 + d]);
            u.z = h2u(Ts[j * 132 + d + 8],       Ts[(j + 1) * 132 + d + 8]);
            u.w = h2u(Ts[(j + 8) * 132 + d + 8], Ts[(j + 9) * 132 + d + 8]);
            dst[(size_t)NI * 8192 + (tt * 4 + KSj) * 32 + (idx & 31)] = u;
        }
    }
}

/* permute NEW kv region (from g_k/g_v; cache copy already done by qkv). */
__global__ void __launch_bounds__(256) permute_new_kernel()
{
    __shared__ float Ts[64 * 132];
    int job = blockIdx.x;
    int isV = job >= 512;
    int jj = job & 511;
    int bh = jj >> 3, tl = jj & 7;
    int b = bh >> 4, h = bh & 15;
    const float* src = (isV ? g_v : g_k) + ((size_t)(b * TGT) + tl * 64) * EMB + h * HD;
    kv_permute_tile(src, (float*)0, Ts, 56 + tl, bh, isV, threadIdx.x);
}

/* ---------------- dense GEMM: C[128,128] = A @ B^T, fp16 fragments ---------- */
#define GSTG 1024
#define GEMM_SMEM (3 * GSTG * 16)

__device__ __forceinline__ void gemm_main(
    const uint4* __restrict__ Ag, const uint4* __restrict__ Bg,
    float c[4][4][4], uint4* S, int tid)
{
    const int lane = tid & 31, wid = tid >> 5;
    const int wm = wid >> 2, wn = wid & 3;

    #pragma unroll
    for (int st = 0; st < 2; st++) {
        #pragma unroll
        for (int i = 0; i < 4; i++) {
            int ch = tid + i * 256;
            int half = ch >> 9, cc = ch & 511;
            int mi = cc >> 6, ksl = (cc >> 5) & 1, l = cc & 31;
            const uint4* src = (half ? Bg : Ag)
                + (size_t)mi * 4096 + (2 * st + ksl) * 32 + l;
            cp16(sm_u32(S + st * GSTG + half * 512 + cc), src);
        }
        CP_COMMIT();
    }

    for (int kt = 0; kt < 64; kt++) {
        if (kt < 63) CP_WAIT(1); else CP_WAIT(0);
        __syncthreads();

        if (kt + 2 < 64) {
            int st = (kt + 2) % 3;
            #pragma unroll
            for (int i = 0; i < 4; i++) {
                int ch = tid + i * 256;
                int half = ch >> 9, cc = ch & 511;
                int mi = cc >> 6, ksl = (cc >> 5) & 1, l = cc & 31;
                const uint4* src = (half ? Bg : Ag)
                    + (size_t)mi * 4096 + (2 * (kt + 2) + ksl) * 32 + l;
                cp16(sm_u32(S + st * GSTG + half * 512 + cc), src);
            }
            CP_COMMIT();
        }

        const uint4* Af = S + (kt % 3) * GSTG;
        const uint4* Bf = Af + 512;
        #pragma unroll
        for (int ks = 0; ks < 2; ks++) {
            uint4 a[4], bu[2];
            #pragma unroll
            for (int mt = 0; mt < 4; mt++)
                a[mt] = Af[((wm * 4 + mt) * 2 + ks) * 32 + lane];
            #pragma unroll
            for (int p = 0; p < 2; p++)
                bu[p] = Bf[((wn * 2 + p) * 2 + ks) * 32 + lane];
            #pragma unroll
            for (int mt = 0; mt < 4; mt++) {
                mma8(c[mt][0], a[mt], bu[0].x, bu[0].y);
                mma8(c[mt][1], a[mt], bu[0].z, bu[0].w);
                mma8(c[mt][2], a[mt], bu[1].x, bu[1].y);
                mma8(c[mt][3], a[mt], bu[1].z, bu[1].w);
            }
        }
    }
}

/* Fused QKV + old-KV permute+copy plane.
   grid (144,16): x<48 -> gemm; x in [48,144) -> permute jobs (1536 blocks). */
__global__ void __launch_bounds__(256, 2) qkv_kernel(
    const float* __restrict__ kc_in, const float* __restrict__ vc_in,
    const float* __restrict__ bq, const float* __restrict__ bk,
    const float* __restrict__ bv,
    float* __restrict__ okc, float* __restrict__ ovc, int write_cache)
{
    extern __shared__ uint4 S[];
    const int tid = threadIdx.x;

    if (blockIdx.x >= 48) {
        float* Ts = (float*)S;
        int pbid = (blockIdx.x - 48) + 96 * blockIdx.y;   /* 0..1535 */
        for (int job = pbid; job < 7168; job += 1536) {
            int isV = job >= 3584;
            int jj = isV ? job - 3584 : job;
            int bh = jj / 56, tt = jj % 56;
            int b = bh >> 4, h = bh & 15;
            size_t off = ((size_t)(b * KVLEN) + tt * 64) * EMB + h * HD;
            const float* src = (isV ? vc_in : kc_in) + off;
            float* cpy = write_cache ? ((isV ? ovc : okc) + off) : (float*)0;
            kv_permute_tile(src, cpy, Ts, tt, bh, isV, tid);
        }
        return;
    }

    const int lane = tid & 31, wid = tid >> 5;
    const int g = lane >> 2, tg = lane & 3;
    const int wm = wid >> 2, wn = wid & 3;
    const int nb = blockIdx.x, mb = blockIdx.y;
    const int sel = nb >> 4, nblk = nb & 15;
    const float* bias = (sel == 0) ? bq : (sel == 1) ? bk : bv;

    const uint4* Ag = g_p + (size_t)mb * 32768;
    const uint4* Bg = g_p + (size_t)(1 + sel) * SLOT_H + (size_t)nblk * 32768;

    float c[4][4][4] = {};
    gemm_main(Ag, Bg, c, S, tid);

    #pragma unroll
    for (int mt = 0; mt < 4; mt++) {
        #pragma unroll
        for (int nt = 0; nt < 4; nt++) {
            int col = nblk * 128 + wn * 32 + nt * 8 + 2 * tg;
            #pragma unroll
            for (int half = 0; half < 2; half++) {
                int m = mb * 128 + wm * 64 + mt * 16 + g + half * 8;
                float v0 = c[mt][nt][half * 2 + 0] + bias[col];
                float v1 = c[mt][nt][half * 2 + 1] + bias[col + 1];
                if (sel == 0) {
                    g_q[(size_t)m * EMB + col]     = v0 * QS2;
                    g_q[(size_t)m * EMB + col + 1] = v1 * QS2;
                } else {
                    float* dst = (sel == 1) ? g_k : g_v;
                    dst[(size_t)m * EMB + col]     = v0;
                    dst[(size_t)m * EMB + col + 1] = v1;
                    if (write_cache) {
                        int bidx = m >> 9, t = m & 511;
                        float* cd = (sel == 1) ? okc : ovc;
                        size_t o = ((size_t)bidx * KVLEN + KVOLD + t) * EMB + col;
                        cd[o] = v0; cd[o + 1] = v1;
                    }
                }
            }
        }
    }
}

/* Output projection: grid (16,16). A = fp16-permuted attn (slot 5). */
__global__ void __launch_bounds__(256, 2) proj_kernel(
    const float* __restrict__ bo, float* __restrict__ out)
{
    extern __shared__ uint4 S[];
    const int tid = threadIdx.x;
    const int lane = tid & 31, wid = tid >> 5;
    const int g = lane >> 2, tg = lane & 3;
    const int wm = wid >> 2, wn = wid & 3;
    const int nblk = blockIdx.x, mb = blockIdx.y;

    const uint4* Ag = g_p + 5 * (size_t)SLOT_H + (size_t)mb * 32768;
    const uint4* Bg = g_p + 4 * (size_t)SLOT_H + (size_t)nblk * 32768;

    float c[4][4][4] = {};
    gemm_main(Ag, Bg, c, S, tid);

    #pragma unroll
    for (int mt = 0; mt < 4; mt++)
        #pragma unroll
        for (int nt = 0; nt < 4; nt++) {
            int col = nblk * 128 + wn * 32 + nt * 8 + 2 * tg;
            #pragma unroll
            for (int half = 0; half < 2; half++) {
                int m = mb * 128 + wm * 64 + mt * 16 + g + half * 8;
                out[(size_t)m * EMB + col]     = c[mt][nt][half * 2 + 0] + bo[col];
                out[(size_t)m * EMB + col + 1] = c[mt][nt][half * 2 + 1] + bo[col + 1];
            }
        }
}

/* ---------------- flash attention: 2 small CTAs/SM, exp2, mask fast path ----
   128 thr, 4 warps; warp w owns rows [w*16, w*16+16) x ALL 64 KV cols.
   Copier plane removed: the old-KV copy is fused into qkv's permute plane,
   so all SMs run attention work and DRAM is uncontended.                    */
#define OVV 2048
#define ATT_SMEM (4096 * 16)
#define NT (KVLEN / 64)

__global__ void __launch_bounds__(128, 2) attn_kernel(
    const float* __restrict__ mask)
{
    extern __shared__ uint4 smq[];

    const int tid  = threadIdx.x;
    const int lane = tid & 31, wid = tid >> 5;          /* wid 0..3 */
    const int g = lane >> 2, tg = lane & 3;
    const int qt = blockIdx.x, h = blockIdx.y, b = blockIdx.z;
    const int mnz = g_mask_nz;                          /* uniform */

    const uint4* gK = g_kp + (size_t)(b * 16 + h) * 65536;
    const uint4* gV = g_vp + (size_t)(b * 16 + h) * 65536;
    const int R0 = wid * 16 + g;
    const int R1 = R0 + 8;
    const float* mrow0 = mask + (size_t)(qt * 64 + R0) * KVLEN;
    const float* mrow1 = mask + (size_t)(qt * 64 + R1) * KVLEN;

    /* prologue: K(0) */
    #pragma unroll
    for (int p = 0; p < 8; p++) {
        int idx = tid + p * 128;
        cp16(sm_u32(smq + idx), gK + idx);
    }
    CP_COMMIT();

    /* Q A-frags in registers (already scaled by QSCALE*log2e) */
    uint4 qr[8];
    {
        const float* qb = g_q + (size_t)(b * TGT + qt * 64 + wid * 16 + g) * EMB + h * HD;
        #pragma unroll
        for (int ks = 0; ks < 8; ks++) {
            const float* p = qb + ks * 16 + 2 * tg;
            float2 v0 = *(const float2*)(p);
            float2 v1 = *(const float2*)(p + 8 * EMB);
            float2 v2 = *(const float2*)(p + 8);
            float2 v3 = *(const float2*)(p + 8 * EMB + 8);
            qr[ks].x = h2u(v0.x, v0.y); qr[ks].y = h2u(v1.x, v1.y);
            qr[ks].z = h2u(v2.x, v2.y); qr[ks].w = h2u(v3.x, v3.y);
        }
    }

    float m0 = -1e30f, m1 = -1e30f, l0 = 0.f, l1 = 0.f;
    float o[16][4] = {};
    uint4 pa[4];   /* deferred P A-frags (previous tile) */

    #pragma unroll 1
    for (int t = 0; t < NT; t++) {
        /* mask prefetch (only when mask is nonzero anywhere) */
        float2 mA[8], mB[8];
        if (mnz) {
            #pragma unroll
            for (int nt = 0; nt < 8; nt++) {
                int col = t * 64 + nt * 8 + 2 * tg;
                mA[nt] = *(const float2*)(mrow0 + col);
                mB[nt] = *(const float2*)(mrow1 + col);
            }
        }

        CP_WAIT(0);          /* group(t-1): K(t) + V(t-1) ready */
        __syncthreads();

        /* issue group(t): K(t+1), V(t) */
        if (t + 1 < NT) {
            #pragma unroll
            for (int p = 0; p < 8; p++) {
                int idx = tid + p * 128;
                cp16(sm_u32(smq + ((t + 1) & 1) * 1024 + idx),
                     gK + (size_t)(t + 1) * 1024 + idx);
            }
        }
        #pragma unroll
        for (int p = 0; p < 8; p++) {
            int idx = tid + p * 128;
            cp16(sm_u32(smq + OVV + (t & 1) * 1024 + idx),
                 gV + (size_t)(idx >> 7) * 8192 + t * 128 + (idx & 127));
        }
        CP_COMMIT();

        const uint4* Kc = smq + (t & 1) * 1024;

        /* S(t) = Q K^T : warp m16 x n64, 8 k16-slices */
        float s[8][4] = {};
        #pragma unroll
        for (int ks = 0; ks < 8; ks++) {
            uint4 a = qr[ks];
            #pragma unroll
            for (int ni = 0; ni < 4; ni++) {
                uint4 KB = Kc[(ni * 8 + ks) * 32 + lane];
                mma8(s[2 * ni],     a, KB.x, KB.y);
                mma8(s[2 * ni + 1], a, KB.z, KB.w);
            }
        }

        /* PV(t-1): queued behind S(t); drains under the softmax below */
        if (t > 0) {
            const uint4* Vc = smq + OVV + ((t & 1) ^ 1) * 1024;
            #pragma unroll
            for (int ksj = 0; ksj < 4; ksj++) {
                uint4 a = pa[ksj];
                #pragma unroll
                for (int ni = 0; ni < 8; ni++) {
                    uint4 v = Vc[(ni * 4 + ksj) * 32 + lane];
                    mma8(o[2 * ni],     a, v.x, v.y);
                    mma8(o[2 * ni + 1], a, v.z, v.w);
                }
            }
        }

        /* softmax(t) in exp2 domain: fully warp-local */
        if (mnz) {
            #pragma unroll
            for (int nt = 0; nt < 8; nt++) {
                s[nt][0] = fmaf(mA[nt].x, LOG2E, s[nt][0]);
                s[nt][1] = fmaf(mA[nt].y, LOG2E, s[nt][1]);
                s[nt][2] = fmaf(mB[nt].x, LOG2E, s[nt][2]);
                s[nt][3] = fmaf(mB[nt].y, LOG2E, s[nt][3]);
            }
        }
        float mx0 = -1e30f, mx1 = -1e30f;
        #pragma unroll
        for (int nt = 0; nt < 8; nt++) {
            mx0 = fmaxf(mx0, fmaxf(s[nt][0], s[nt][1]));
            mx1 = fmaxf(mx1, fmaxf(s[nt][2], s[nt][3]));
        }
        mx0 = fmaxf(mx0, __shfl_xor_sync(0xffffffffu, mx0, 1));
        mx0 = fmaxf(mx0, __shfl_xor_sync(0xffffffffu, mx0, 2));
        mx1 = fmaxf(mx1, __shfl_xor_sync(0xffffffffu, mx1, 1));
        mx1 = fmaxf(mx1, __shfl_xor_sync(0xffffffffu, mx1, 2));
        float mn0 = fmaxf(m0, mx0);
        float mn1 = fmaxf(m1, mx1);

        float s0s = 0.f, s1s = 0.f;
        #pragma unroll
        for (int nt = 0; nt < 8; nt++) {
            s[nt][0] = exp2f(s[nt][0] - mn0);
            s[nt][1] = exp2f(s[nt][1] - mn0);
            s[nt][2] = exp2f(s[nt][2] - mn1);
            s[nt][3] = exp2f(s[nt][3] - mn1);
            s0s += s[nt][0] + s[nt][1];
            s1s += s[nt][2] + s[nt][3];
        }
        s0s += __shfl_xor_sync(0xffffffffu, s0s, 1);
        s0s += __shfl_xor_sync(0xffffffffu, s0s, 2);
        s1s += __shfl_xor_sync(0xffffffffu, s1s, 1);
        s1s += __shfl_xor_sync(0xffffffffu, s1s, 2);

        float sc0 = exp2f(m0 - mn0), sc1 = exp2f(m1 - mn1);
        l0 = l0 * sc0 + s0s;
        l1 = l1 * sc1 + s1s;
        m0 = mn0; m1 = mn1;
        #pragma unroll
        for (int nt = 0; nt < 16; nt++) {
            o[nt][0] *= sc0; o[nt][1] *= sc0;
            o[nt][2] *= sc1; o[nt][3] *= sc1;
        }

        /* pack P c-frags -> A-frags IN-LANE */
        #pragma unroll
        for (int KS = 0; KS < 4; KS++) {
            pa[KS].x = h2u(s[2 * KS][0],     s[2 * KS][1]);
            pa[KS].y = h2u(s[2 * KS][2],     s[2 * KS][3]);
            pa[KS].z = h2u(s[2 * KS + 1][0], s[2 * KS + 1][1]);
            pa[KS].w = h2u(s[2 * KS + 1][2], s[2 * KS + 1][3]);
        }
    }

    /* drain: PV(NT-1) */
    CP_WAIT(0);
    __syncthreads();
    {
        const uint4* Vc = smq + OVV + ((NT - 1) & 1) * 1024;
        #pragma unroll
        for (int ksj = 0; ksj < 4; ksj++) {
            uint4 a = pa[ksj];
            #pragma unroll
            for (int ni = 0; ni < 8; ni++) {
                uint4 v = Vc[(ni * 4 + ksj) * 32 + lane];
                mma8(o[2 * ni],     a, v.x, v.y);
                mma8(o[2 * ni + 1], a, v.z, v.w);
            }
        }
    }

    /* fused epilogue: normalize, stage f32, write fp16 A-frags to slot 5 */
    __syncthreads();
    float* St = (float*)smq;   /* 64 x 132 floats = 33.8 KB */
    {
        float inv0 = 1.f / l0, inv1 = 1.f / l1;
        #pragma unroll
        for (int nt = 0; nt < 16; nt++) {
            int c = nt * 8 + 2 * tg;
            St[R0 * 132 + c]     = o[nt][0] * inv0;
            St[R0 * 132 + c + 1] = o[nt][1] * inv0;
            St[R1 * 132 + c]     = o[nt][2] * inv1;
            St[R1 * 132 + c + 1] = o[nt][3] * inv1;
        }
    }
    __syncthreads();
    {
        uint4* gp5 = g_p + 5 * (size_t)SLOT_H;
        const int gMIb = b * 32 + qt * 4;   /* (b*TGT + qt*64)/16 */
        #pragma unroll
        for (int i = 0; i < 8; i++) {
            int MI = i >> 1;
            int ksl = wid * 2 + (i & 1);
            int r = MI * 16 + g, c = ksl * 16 + 2 * tg;
            uint4 u;
            u.x = h2u(St[r * 132 + c],           St[r * 132 + c + 1]);
            u.y = h2u(St[(r + 8) * 132 + c],     St[(r + 8) * 132 + c + 1]);
            u.z = h2u(St[r * 132 + c + 8],       St[r * 132 + c + 9]);
            u.w = h2u(St[(r + 8) * 132 + c + 8], St[(r + 8) * 132 + c + 9]);
            gp5[((size_t)(gMIb + MI) * 128 + (h * 8 + ksl)) * 32 + lane] = u;
        }
    }
}

/* ------------------------------------------------------------------ */
extern "C" void kernel_launch(void* const* d_in, const int* in_sizes, int n_in,
                              void* d_out, int out_size)
{
    const float* x       = (const float*)d_in[0];
    const float* k_cache = (const float*)d_in[1];
    const float* v_cache = (const float*)d_in[2];
    const float* mask    = (const float*)d_in[3];
    const float* wq = (const float*)d_in[4];
    const float* bq = (const float*)d_in[5];
    const float* wk = (const float*)d_in[6];
    const float* bk = (const float*)d_in[7];
    const float* wv = (const float*)d_in[8];
    const float* bv = (const float*)d_in[9];
    const float* wo = (const float*)d_in[10];
    const float* bo = (const float*)d_in[11];

    float* out = (float*)d_out;
    long long need = (long long)MROWS * EMB + 2LL * BSZ * KVLEN * EMB;
    int write_cache = ((long long)out_size >= need) ? 1 : 0;
    float* okc = out + (size_t)MROWS * EMB;
    float* ovc = okc + (size_t)BSZ * KVLEN * EMB;

    cudaFuncSetAttribute(attn_kernel,
                         cudaFuncAttributeMaxDynamicSharedMemorySize, ATT_SMEM);
    cudaFuncSetAttribute(qkv_kernel,
                         cudaFuncAttributeMaxDynamicSharedMemorySize, GEMM_SMEM);
    cudaFuncSetAttribute(proj_kernel,
                         cudaFuncAttributeMaxDynamicSharedMemorySize, GEMM_SMEM);

    flag_init_kernel<<<1, 1>>>();
    mask_scan_kernel<<<512, 256>>>(mask);
    convert5_kernel<<<dim3(2048, 5), 256>>>(x, wq, wk, wv, wo);
    qkv_kernel<<<dim3(144, 16), 256, GEMM_SMEM>>>(k_cache, v_cache,
                                                  bq, bk, bv, okc, ovc, write_cache);
    permute_new_kernel<<<1024, 256>>>();
    attn_kernel<<<dim3(8, 16, BSZ), 128, ATT_SMEM>>>(mask);
    proj_kernel<<<dim3(16, 16), 256, GEMM_SMEM>>>(bo, out);
}